// round 2
// baseline (speedup 1.0000x reference)
#include <cuda_runtime.h>
#include <cuda_bf16.h>
#include <cstdint>

// Problem constants
#define BATCH 4
#define HW    4096
#define CH    256
#define PROJ_SZ (BATCH * HW * CH)        // 4,194,304 floats per projection

// Scratch (device globals: allowed; no runtime allocation)
__device__ float g_P[5u * PROJ_SZ];                 // xw1,xw2,xw3,gw1,gw2  (84 MB)
__device__ float g_Sx[(size_t)BATCH * HW * HW];     // 268 MB
__device__ float g_Sg[(size_t)BATCH * HW * HW];     // 268 MB
__device__ float g_L[BATCH * HW];
__device__ float g_pmax[BATCH * HW];
__device__ float g_invZ2[BATCH * HW];

#define BM 64
#define BN 64
#define BKC 16

// ---------------------------------------------------------------------------
// proj: C[16384,256] = A[16384,256] @ W[256,256] + bias ;  C -> g_P[which]
// ---------------------------------------------------------------------------
__global__ void proj_gemm(const float* __restrict__ A, const float* __restrict__ W,
                          const float* __restrict__ bias, int which) {
    __shared__ float As[BKC][BM];
    __shared__ float Bs[BKC][BN];
    const int tid = threadIdx.x;
    const int m0 = blockIdx.y * BM;
    const int n0 = blockIdx.x * BN;
    const int K = CH, N = CH;
    const int tr = tid >> 4, tc = tid & 15;
    const int arow = tid >> 2, aq = tid & 3;   // A: 64 rows x 4 float4
    const int brow = tid >> 4, bq = tid & 15;  // W: 16 krows x 16 float4

    float acc[4][4] = {};
    for (int k0 = 0; k0 < K; k0 += BKC) {
        float4 av = *(const float4*)&A[(size_t)(m0 + arow) * K + k0 + aq * 4];
        As[aq * 4 + 0][arow] = av.x;
        As[aq * 4 + 1][arow] = av.y;
        As[aq * 4 + 2][arow] = av.z;
        As[aq * 4 + 3][arow] = av.w;
        *(float4*)&Bs[brow][bq * 4] =
            *(const float4*)&W[(size_t)(k0 + brow) * N + n0 + bq * 4];
        __syncthreads();
#pragma unroll
        for (int k = 0; k < BKC; k++) {
            float4 a = *(const float4*)&As[k][tr * 4];
            float4 b = *(const float4*)&Bs[k][tc * 4];
            float av_[4] = {a.x, a.y, a.z, a.w};
            float bv_[4] = {b.x, b.y, b.z, b.w};
#pragma unroll
            for (int i = 0; i < 4; i++)
#pragma unroll
                for (int j = 0; j < 4; j++) acc[i][j] += av_[i] * bv_[j];
        }
        __syncthreads();
    }
    float* C = g_P + (size_t)which * PROJ_SZ;
#pragma unroll
    for (int i = 0; i < 4; i++) {
        float4 r;
        r.x = acc[i][0] + bias[n0 + tc * 4 + 0];
        r.y = acc[i][1] + bias[n0 + tc * 4 + 1];
        r.z = acc[i][2] + bias[n0 + tc * 4 + 2];
        r.w = acc[i][3] + bias[n0 + tc * 4 + 3];
        *(float4*)&C[(size_t)(m0 + tr * 4 + i) * N + n0 + tc * 4] = r;
    }
}

// ---------------------------------------------------------------------------
// scores: Dst[4096,4096] = A[4096,256] @ B[4096,256]^T   (per batch, per branch)
// ---------------------------------------------------------------------------
__global__ void score_gemm(int bat, int a_which, int b_which, int dest) {
    __shared__ float As[BKC][BM];
    __shared__ float Bs[BKC][BN];
    const float* A  = g_P + (size_t)a_which * PROJ_SZ + (size_t)bat * HW * CH;
    const float* Bm = g_P + (size_t)b_which * PROJ_SZ + (size_t)bat * HW * CH;
    float* Dst = (dest ? g_Sg : g_Sx) + (size_t)bat * HW * HW;
    const int tid = threadIdx.x;
    const int m0 = blockIdx.y * BM;
    const int n0 = blockIdx.x * BN;
    const int K = CH;
    const int tr = tid >> 4, tc = tid & 15;
    const int arow = tid >> 2, aq = tid & 3;

    float acc[4][4] = {};
    for (int k0 = 0; k0 < K; k0 += BKC) {
        float4 av = *(const float4*)&A[(size_t)(m0 + arow) * K + k0 + aq * 4];
        As[aq * 4 + 0][arow] = av.x;
        As[aq * 4 + 1][arow] = av.y;
        As[aq * 4 + 2][arow] = av.z;
        As[aq * 4 + 3][arow] = av.w;
        float4 bv = *(const float4*)&Bm[(size_t)(n0 + arow) * K + k0 + aq * 4];
        Bs[aq * 4 + 0][arow] = bv.x;
        Bs[aq * 4 + 1][arow] = bv.y;
        Bs[aq * 4 + 2][arow] = bv.z;
        Bs[aq * 4 + 3][arow] = bv.w;
        __syncthreads();
#pragma unroll
        for (int k = 0; k < BKC; k++) {
            float4 a = *(const float4*)&As[k][tr * 4];
            float4 b = *(const float4*)&Bs[k][tc * 4];
            float av_[4] = {a.x, a.y, a.z, a.w};
            float bv_[4] = {b.x, b.y, b.z, b.w};
#pragma unroll
            for (int i = 0; i < 4; i++)
#pragma unroll
                for (int j = 0; j < 4; j++) acc[i][j] += av_[i] * bv_[j];
        }
        __syncthreads();
    }
#pragma unroll
    for (int i = 0; i < 4; i++) {
        float4 r;
        r.x = acc[i][0]; r.y = acc[i][1]; r.z = acc[i][2]; r.w = acc[i][3];
        *(float4*)&Dst[(size_t)(m0 + tr * 4 + i) * HW + n0 + tc * 4] = r;
    }
}

// ---------------------------------------------------------------------------
// per-row softmax statistics (one block = one global row, both Sx & Sg rows in smem)
//   L = mx + ln Zx + mg + ln Zg ;  pmax = exp(Smax - L) ;
//   Z2 = sum_j exp( exp(S - L) - pmax )
// ---------------------------------------------------------------------------
__device__ __forceinline__ float block_max(float v, float* red) {
    int tid = threadIdx.x;
    red[tid] = v; __syncthreads();
    for (int s = 128; s > 0; s >>= 1) {
        if (tid < s) red[tid] = fmaxf(red[tid], red[tid + s]);
        __syncthreads();
    }
    float r = red[0]; __syncthreads();
    return r;
}
__device__ __forceinline__ float block_sum(float v, float* red) {
    int tid = threadIdx.x;
    red[tid] = v; __syncthreads();
    for (int s = 128; s > 0; s >>= 1) {
        if (tid < s) red[tid] += red[tid + s];
        __syncthreads();
    }
    float r = red[0]; __syncthreads();
    return r;
}

__global__ void row_stats_kernel() {
    __shared__ float sx[HW];
    __shared__ float sg[HW];
    __shared__ float red[256];
    const int row = blockIdx.x;          // b*HW + i
    const int tid = threadIdx.x;
    const float* px = g_Sx + (size_t)row * HW;
    const float* pg = g_Sg + (size_t)row * HW;
    for (int t = tid; t < HW / 4; t += 256) {
        *(float4*)&sx[t * 4] = *(const float4*)&px[t * 4];
        *(float4*)&sg[t * 4] = *(const float4*)&pg[t * 4];
    }
    __syncthreads();

    float v = -1e30f;
    for (int t = tid; t < HW; t += 256) v = fmaxf(v, sx[t]);
    const float mx = block_max(v, red);

    float s = 0.f;
    for (int t = tid; t < HW; t += 256) s += __expf(sx[t] - mx);
    const float Zx = block_sum(s, red);

    v = -1e30f;
    for (int t = tid; t < HW; t += 256) v = fmaxf(v, sg[t]);
    const float mg = block_max(v, red);

    s = 0.f;
    for (int t = tid; t < HW; t += 256) s += __expf(sg[t] - mg);
    const float Zg = block_sum(s, red);

    v = -1e30f;
    for (int t = tid; t < HW; t += 256) v = fmaxf(v, sx[t] + sg[t]);
    const float Smax = block_max(v, red);

    const float L = mx + __logf(Zx) + mg + __logf(Zg);
    const float pmax = __expf(Smax - L);

    s = 0.f;
    for (int t = tid; t < HW; t += 256)
        s += __expf(__expf(sx[t] + sg[t] - L) - pmax);
    const float Z2 = block_sum(s, red);

    if (tid == 0) {
        g_L[row] = L;
        g_pmax[row] = pmax;
        g_invZ2[row] = 1.f / Z2;
    }
}

// ---------------------------------------------------------------------------
// out[b,j,c] = x[b,j,c] + sum_i attn(i,j) * xw3[b,i,c]
//   attn(i,j) = exp( exp(Sx+Sg - L_i) - pmax_i ) * invZ2_i
// tile: 64 (j) x 128 (c), K-chunk (i) = 16, micro 4x8, 256 threads
// ---------------------------------------------------------------------------
__global__ void out_kernel(const float* __restrict__ x_in, float* __restrict__ out) {
    __shared__ float Ws[BKC][64];
    __shared__ float Xs[BKC][128];
    const int bat = blockIdx.z;
    const int j0 = blockIdx.y * 64;
    const int c0 = blockIdx.x * 128;
    const float* Sxb = g_Sx + (size_t)bat * HW * HW;
    const float* Sgb = g_Sg + (size_t)bat * HW * HW;
    const float* X3 = g_P + 2u * PROJ_SZ + (size_t)bat * HW * CH;
    const float* Lp = g_L + bat * HW;
    const float* Pm = g_pmax + bat * HW;
    const float* Iz = g_invZ2 + bat * HW;

    const int tid = threadIdx.x;
    const int tr = tid >> 4, tc = tid & 15;
    const int jj = tid & 63, ib = tid >> 6;

    float acc[4][8] = {};
    for (int i0 = 0; i0 < HW; i0 += BKC) {
#pragma unroll
        for (int r = 0; r < 4; r++) {
            const int ii = ib + r * 4;
            const int i = i0 + ii;
            const float sv = Sxb[(size_t)i * HW + j0 + jj] + Sgb[(size_t)i * HW + j0 + jj];
            Ws[ii][jj] = __expf(__expf(sv - Lp[i]) - Pm[i]) * Iz[i];
        }
#pragma unroll
        for (int r = 0; r < 2; r++) {
            const int idx = tid + r * 256;    // 0..511
            const int ii = idx >> 5;          // 0..15
            const int cq = idx & 31;
            *(float4*)&Xs[ii][cq * 4] =
                *(const float4*)&X3[(size_t)(i0 + ii) * CH + c0 + cq * 4];
        }
        __syncthreads();
#pragma unroll
        for (int k = 0; k < BKC; k++) {
            float4 w = *(const float4*)&Ws[k][tr * 4];
            float4 xa = *(const float4*)&Xs[k][tc * 8];
            float4 xb = *(const float4*)&Xs[k][tc * 8 + 4];
            float wv[4] = {w.x, w.y, w.z, w.w};
            float xv[8] = {xa.x, xa.y, xa.z, xa.w, xb.x, xb.y, xb.z, xb.w};
#pragma unroll
            for (int i = 0; i < 4; i++)
#pragma unroll
                for (int j = 0; j < 8; j++) acc[i][j] += wv[i] * xv[j];
        }
        __syncthreads();
    }
#pragma unroll
    for (int i = 0; i < 4; i++) {
        const size_t base = ((size_t)bat * HW + j0 + tr * 4 + i) * CH + c0 + tc * 8;
#pragma unroll
        for (int j = 0; j < 8; j += 4) {
            float4 xv = *(const float4*)&x_in[base + j];
            float4 r;
            r.x = acc[i][j + 0] + xv.x;
            r.y = acc[i][j + 1] + xv.y;
            r.z = acc[i][j + 2] + xv.z;
            r.w = acc[i][j + 3] + xv.w;
            *(float4*)&out[base + j] = r;
        }
    }
}

// ---------------------------------------------------------------------------
extern "C" void kernel_launch(void* const* d_in, const int* in_sizes, int n_in,
                              void* d_out, int out_size) {
    (void)in_sizes; (void)n_in; (void)out_size;
    const float* x   = (const float*)d_in[0];
    const float* g   = (const float*)d_in[1];
    const float* Wx1 = (const float*)d_in[2];
    const float* bx1 = (const float*)d_in[3];
    const float* Wx2 = (const float*)d_in[4];
    const float* bx2 = (const float*)d_in[5];
    const float* Wx3 = (const float*)d_in[6];
    const float* bx3 = (const float*)d_in[7];
    const float* Wg1 = (const float*)d_in[8];
    const float* bg1 = (const float*)d_in[9];
    const float* Wg2 = (const float*)d_in[10];
    const float* bg2 = (const float*)d_in[11];
    float* out = (float*)d_out;

    dim3 pg(CH / BN, (BATCH * HW) / BM);   // (4, 256)
    proj_gemm<<<pg, 256>>>(x, Wx1, bx1, 0);
    proj_gemm<<<pg, 256>>>(x, Wx2, bx2, 1);
    proj_gemm<<<pg, 256>>>(x, Wx3, bx3, 2);
    proj_gemm<<<pg, 256>>>(g, Wg1, bg1, 3);
    proj_gemm<<<pg, 256>>>(g, Wg2, bg2, 4);

    dim3 sg(HW / BN, HW / BM);             // (64, 64)
    for (int b = 0; b < BATCH; b++) {
        score_gemm<<<sg, 256>>>(b, 1, 0, 0);   // Sx = xw2 @ xw1^T
        score_gemm<<<sg, 256>>>(b, 4, 3, 1);   // Sg = gw2 @ gw1^T
    }

    row_stats_kernel<<<BATCH * HW, 256>>>();

    dim3 og(CH / 128, HW / 64, BATCH);     // (2, 64, 4)
    out_kernel<<<og, 256>>>(x, out);
}

// round 3
// speedup vs baseline: 4.1603x; 4.1603x over previous
#include <cuda_runtime.h>
#include <cuda_bf16.h>
#include <cstdint>

#define BATCH 4
#define HW    4096
#define CH    256
#define PROJ_SZ (BATCH * HW * CH)

// ---- device scratch ----
__device__ __nv_bfloat16 g_Pb[5u * PROJ_SZ];                 // bf16 projections (42MB)
__device__ float         g_X3[PROJ_SZ];                      // xw3 fp32 (64MB? 16MB)
__device__ __nv_bfloat16 g_X3p[PROJ_SZ];                     // invZ2-folded xw3 bf16
__device__ __nv_bfloat16 g_Sx[(size_t)BATCH * HW * HW];      // 134MB
__device__ __nv_bfloat16 g_Sg[(size_t)BATCH * HW * HW];      // 134MB
__device__ __nv_bfloat16 g_V[(size_t)BATCH * HW * HW];       // u-1, 134MB
__device__ float g_invZ2[BATCH * HW];
__device__ float g_colpart[128 * CH];
__device__ float g_colsum[BATCH * CH];

// ---- mma helpers ----
__device__ __forceinline__ uint32_t cvta_s(const void* p) {
    return (uint32_t)__cvta_generic_to_shared(p);
}
__device__ __forceinline__ void ldsm4(uint32_t* r, uint32_t a) {
    asm volatile("ldmatrix.sync.aligned.m8n8.x4.shared.b16 {%0,%1,%2,%3},[%4];"
                 : "=r"(r[0]), "=r"(r[1]), "=r"(r[2]), "=r"(r[3]) : "r"(a));
}
__device__ __forceinline__ void ldsm4t(uint32_t* r, uint32_t a) {
    asm volatile("ldmatrix.sync.aligned.m8n8.x4.trans.shared.b16 {%0,%1,%2,%3},[%4];"
                 : "=r"(r[0]), "=r"(r[1]), "=r"(r[2]), "=r"(r[3]) : "r"(a));
}
__device__ __forceinline__ void mma16816(float* c, const uint32_t* a, const uint32_t* b) {
    asm volatile("mma.sync.aligned.m16n8k16.row.col.f32.bf16.bf16.f32 "
                 "{%0,%1,%2,%3},{%4,%5,%6,%7},{%8,%9},{%0,%1,%2,%3};"
                 : "+f"(c[0]), "+f"(c[1]), "+f"(c[2]), "+f"(c[3])
                 : "r"(a[0]), "r"(a[1]), "r"(a[2]), "r"(a[3]), "r"(b[0]), "r"(b[1]));
}
__device__ __forceinline__ void cpa16(void* s, const void* g) {
    asm volatile("cp.async.cg.shared.global [%0],[%1],16;" :: "r"(cvta_s(s)), "l"(g));
}
#define CP_COMMIT asm volatile("cp.async.commit_group;")
#define CP_WAIT0  asm volatile("cp.async.wait_group 0;")

// ---------------------------------------------------------------------------
// proj: fp32 SIMT GEMM  C = A[16384,256] @ W[256,256] + bias
//   writes bf16 to g_Pb[which]; if which==2 also fp32 to g_X3
// ---------------------------------------------------------------------------
__global__ void proj_gemm(const float* __restrict__ A, const float* __restrict__ W,
                          const float* __restrict__ bias, int which) {
    __shared__ float As[16][64];
    __shared__ float Bs[16][64];
    const int tid = threadIdx.x;
    const int m0 = blockIdx.y * 64;
    const int n0 = blockIdx.x * 64;
    const int tr = tid >> 4, tc = tid & 15;
    const int arow = tid >> 2, aq = tid & 3;
    const int brow = tid >> 4, bq = tid & 15;

    float acc[4][4] = {};
    for (int k0 = 0; k0 < CH; k0 += 16) {
        float4 av = *(const float4*)&A[(size_t)(m0 + arow) * CH + k0 + aq * 4];
        As[aq * 4 + 0][arow] = av.x; As[aq * 4 + 1][arow] = av.y;
        As[aq * 4 + 2][arow] = av.z; As[aq * 4 + 3][arow] = av.w;
        *(float4*)&Bs[brow][bq * 4] = *(const float4*)&W[(size_t)(k0 + brow) * CH + n0 + bq * 4];
        __syncthreads();
#pragma unroll
        for (int k = 0; k < 16; k++) {
            float4 a = *(const float4*)&As[k][tr * 4];
            float4 b = *(const float4*)&Bs[k][tc * 4];
            float av_[4] = {a.x, a.y, a.z, a.w};
            float bv_[4] = {b.x, b.y, b.z, b.w};
#pragma unroll
            for (int i = 0; i < 4; i++)
#pragma unroll
                for (int j = 0; j < 4; j++) acc[i][j] += av_[i] * bv_[j];
        }
        __syncthreads();
    }
    __nv_bfloat16* Cb = g_Pb + (size_t)which * PROJ_SZ;
#pragma unroll
    for (int i = 0; i < 4; i++) {
        float r[4];
#pragma unroll
        for (int j = 0; j < 4; j++) r[j] = acc[i][j] + bias[n0 + tc * 4 + j];
        const size_t off = (size_t)(m0 + tr * 4 + i) * CH + n0 + tc * 4;
        __nv_bfloat162 p0, p1;
        p0.x = __float2bfloat16(r[0]); p0.y = __float2bfloat16(r[1]);
        p1.x = __float2bfloat16(r[2]); p1.y = __float2bfloat16(r[3]);
        *(__nv_bfloat162*)&Cb[off] = p0;
        *(__nv_bfloat162*)&Cb[off + 2] = p1;
        if (which == 2) {
            float4 f; f.x = r[0]; f.y = r[1]; f.z = r[2]; f.w = r[3];
            *(float4*)&g_X3[off] = f;
        }
    }
}

// ---------------------------------------------------------------------------
// score mma: Dst[4096,4096](bf16) = A[4096,256] @ B[4096,256]^T, bf16 tensor cores
// tile 128x128x32, 256 thr (8 warps: 2m x 4n, warp 64x32), cp.async double-buffer
// ---------------------------------------------------------------------------
__global__ __launch_bounds__(256) void score_mma(int bat, int aw, int bw, int dest) {
    __shared__ __align__(16) __nv_bfloat16 As[2][128][40];
    __shared__ __align__(16) __nv_bfloat16 Bs[2][128][40];
    const __nv_bfloat16* A  = g_Pb + (size_t)aw * PROJ_SZ + (size_t)bat * HW * CH
                              + (size_t)blockIdx.y * 128 * CH;
    const __nv_bfloat16* Bm = g_Pb + (size_t)bw * PROJ_SZ + (size_t)bat * HW * CH
                              + (size_t)blockIdx.x * 128 * CH;
    __nv_bfloat16* Dst = (dest ? g_Sg : g_Sx) + (size_t)bat * HW * HW;
    const int tid = threadIdx.x, lane = tid & 31, wid = tid >> 5;
    const int wm = wid & 1, wn = wid >> 1;
    const int lrow = tid >> 1;        // 0..127
    const int lch = (tid & 1) * 2;    // chunk base

    float acc[4][4][4] = {};

#pragma unroll 1
    for (int s = 0; s < 8; s++) {
        if (s == 0) {
#pragma unroll
            for (int q = 0; q < 2; q++) {
                cpa16(&As[0][lrow][(lch + q) * 8], A + (size_t)lrow * CH + (lch + q) * 8);
                cpa16(&Bs[0][lrow][(lch + q) * 8], Bm + (size_t)lrow * CH + (lch + q) * 8);
            }
            CP_COMMIT;
        }
        CP_WAIT0; __syncthreads();
        if (s < 7) {
            const int k0 = (s + 1) * 32, st2 = (s + 1) & 1;
#pragma unroll
            for (int q = 0; q < 2; q++) {
                cpa16(&As[st2][lrow][(lch + q) * 8], A + (size_t)lrow * CH + k0 + (lch + q) * 8);
                cpa16(&Bs[st2][lrow][(lch + q) * 8], Bm + (size_t)lrow * CH + k0 + (lch + q) * 8);
            }
        }
        CP_COMMIT;
        const int st = s & 1;
#pragma unroll
        for (int kk = 0; kk < 2; kk++) {
            uint32_t a[4][4], b[4][2];
#pragma unroll
            for (int mf = 0; mf < 4; mf++) {
                const int row = wm * 64 + mf * 16 + (lane & 15);
                const int ko = kk * 16 + (lane >> 4) * 8;
                ldsm4(a[mf], cvta_s(&As[st][row][ko]));
            }
#pragma unroll
            for (int np = 0; np < 2; np++) {
                const int row = wn * 32 + np * 16 + (lane & 7) + (lane >> 4) * 8;
                const int ko = kk * 16 + ((lane >> 3) & 1) * 8;
                uint32_t r[4];
                ldsm4(r, cvta_s(&Bs[st][row][ko]));
                b[2 * np][0] = r[0]; b[2 * np][1] = r[1];
                b[2 * np + 1][0] = r[2]; b[2 * np + 1][1] = r[3];
            }
#pragma unroll
            for (int mf = 0; mf < 4; mf++)
#pragma unroll
                for (int nf = 0; nf < 4; nf++) mma16816(acc[mf][nf], a[mf], b[nf]);
        }
        __syncthreads();
    }
    const int m0 = blockIdx.y * 128 + wm * 64, n0 = blockIdx.x * 128 + wn * 32;
#pragma unroll
    for (int mf = 0; mf < 4; mf++) {
        const int r0 = m0 + mf * 16 + (lane >> 2);
#pragma unroll
        for (int nf = 0; nf < 4; nf++) {
            const int col = n0 + nf * 8 + (lane & 3) * 2;
            __nv_bfloat162 v0, v1;
            v0.x = __float2bfloat16(acc[mf][nf][0]); v0.y = __float2bfloat16(acc[mf][nf][1]);
            v1.x = __float2bfloat16(acc[mf][nf][2]); v1.y = __float2bfloat16(acc[mf][nf][3]);
            *(__nv_bfloat162*)&Dst[(size_t)r0 * HW + col] = v0;
            *(__nv_bfloat162*)&Dst[(size_t)(r0 + 8) * HW + col] = v1;
        }
    }
}

// ---------------------------------------------------------------------------
// per-row stats + materialize v = exp(p - pmax) - 1  (bf16)
// ---------------------------------------------------------------------------
__device__ __forceinline__ float blk_max(float v, float* red) {
    int tid = threadIdx.x;
    red[tid] = v; __syncthreads();
    for (int s = 128; s > 0; s >>= 1) {
        if (tid < s) red[tid] = fmaxf(red[tid], red[tid + s]);
        __syncthreads();
    }
    float r = red[0]; __syncthreads();
    return r;
}
__device__ __forceinline__ float blk_sum(float v, float* red) {
    int tid = threadIdx.x;
    red[tid] = v; __syncthreads();
    for (int s = 128; s > 0; s >>= 1) {
        if (tid < s) red[tid] += red[tid + s];
        __syncthreads();
    }
    float r = red[0]; __syncthreads();
    return r;
}

__global__ void row_stats_kernel() {
    __shared__ float sx[HW];
    __shared__ float sg[HW];
    __shared__ float red[256];
    const int row = blockIdx.x;
    const int tid = threadIdx.x;
    const __nv_bfloat16* px = g_Sx + (size_t)row * HW;
    const __nv_bfloat16* pg = g_Sg + (size_t)row * HW;

    for (int t = tid; t < HW / 4; t += 256) {
        __nv_bfloat162 x0 = *(const __nv_bfloat162*)&px[t * 4];
        __nv_bfloat162 x1 = *(const __nv_bfloat162*)&px[t * 4 + 2];
        __nv_bfloat162 g0 = *(const __nv_bfloat162*)&pg[t * 4];
        __nv_bfloat162 g1 = *(const __nv_bfloat162*)&pg[t * 4 + 2];
        sx[t * 4 + 0] = __bfloat162float(x0.x); sx[t * 4 + 1] = __bfloat162float(x0.y);
        sx[t * 4 + 2] = __bfloat162float(x1.x); sx[t * 4 + 3] = __bfloat162float(x1.y);
        sg[t * 4 + 0] = __bfloat162float(g0.x); sg[t * 4 + 1] = __bfloat162float(g0.y);
        sg[t * 4 + 2] = __bfloat162float(g1.x); sg[t * 4 + 3] = __bfloat162float(g1.y);
    }
    __syncthreads();

    float v = -1e30f;
    for (int t = tid; t < HW; t += 256) v = fmaxf(v, sx[t]);
    const float mx = blk_max(v, red);
    float s = 0.f;
    for (int t = tid; t < HW; t += 256) s += __expf(sx[t] - mx);
    const float Zx = blk_sum(s, red);

    v = -1e30f;
    for (int t = tid; t < HW; t += 256) v = fmaxf(v, sg[t]);
    const float mg = blk_max(v, red);
    s = 0.f;
    for (int t = tid; t < HW; t += 256) s += __expf(sg[t] - mg);
    const float Zg = blk_sum(s, red);

    v = -1e30f;
    for (int t = tid; t < HW; t += 256) v = fmaxf(v, sx[t] + sg[t]);
    const float m2 = blk_max(v, red);

    const float L = mx + mg + __logf(Zx) + __logf(Zg);
    const float pmax = __expf(m2 - L);

    __nv_bfloat16* vo = g_V + (size_t)row * HW;
    s = 0.f;
    for (int t = tid; t < HW; t += 256) {
        const float p = __expf(sx[t] + sg[t] - L);
        const float tt = p - pmax;   // in [-pmax, 0]
        // expm1(tt) via series (pmax << 1, so high accuracy)
        const float vv = tt * (1.f + tt * (0.5f + tt * (0.16666667f + tt * 0.04166667f)));
        s += vv;
        vo[t] = __float2bfloat16(vv);
    }
    const float Z2 = (float)HW + blk_sum(s, red);
    if (tid == 0) g_invZ2[row] = 1.f / Z2;
}

// ---------------------------------------------------------------------------
// fold: xw3p[i,c] = bf16(xw3[i,c] * invZ2[i]); partial column sums (fp32)
// ---------------------------------------------------------------------------
__global__ void fold_kernel() {
    const int blk = blockIdx.x;              // 0..127
    const int bat = blk >> 5;
    const int i0 = (blk & 31) * 128;
    const int c = threadIdx.x;               // 0..255
    const float* X = g_X3 + ((size_t)bat * HW + i0) * CH;
    __nv_bfloat16* P = g_X3p + ((size_t)bat * HW + i0) * CH;
    const float* iz = g_invZ2 + bat * HW + i0;
    float s = 0.f;
#pragma unroll 4
    for (int r = 0; r < 128; r++) {
        const float val = X[(size_t)r * CH + c] * iz[r];
        s += val;
        P[(size_t)r * CH + c] = __float2bfloat16(val);
    }
    g_colpart[blk * CH + c] = s;
}
__global__ void colsum_reduce() {
    const int bat = blockIdx.x, c = threadIdx.x;
    float s = 0.f;
    for (int k = 0; k < 32; k++) s += g_colpart[(bat * 32 + k) * CH + c];
    g_colsum[bat * CH + c] = s;
}

// ---------------------------------------------------------------------------
// out mma: out[b,j,c] = x + colsum[b,c] + sum_i v[i,j]*xw3p[i,c]
// M=4096(j), N=128-tile of c, K=4096(i); trans-ldmatrix on both operands
// ---------------------------------------------------------------------------
__global__ __launch_bounds__(256) void out_mma(const float* __restrict__ x_in,
                                               float* __restrict__ out) {
    __shared__ __align__(16) __nv_bfloat16 Vs[2][32][136];
    __shared__ __align__(16) __nv_bfloat16 Xs[2][32][136];
    __shared__ float cs_s[128];
    const int bat = blockIdx.z;
    const int j0 = blockIdx.y * 128, c0 = blockIdx.x * 128;
    const __nv_bfloat16* V = g_V + (size_t)bat * HW * HW;      // [i][j]
    const __nv_bfloat16* X = g_X3p + (size_t)bat * HW * CH;    // [i][c]
    const int tid = threadIdx.x, lane = tid & 31, wid = tid >> 5;
    const int wm = wid & 1, wn = wid >> 1;
    const int vrow = tid >> 3;          // 0..31
    const int vch = (tid & 7) * 2;

    if (tid < 128) cs_s[tid] = g_colsum[bat * CH + c0 + tid];

    float acc[4][4][4] = {};

#pragma unroll 1
    for (int s = 0; s < 128; s++) {
        if (s == 0) {
#pragma unroll
            for (int q = 0; q < 2; q++) {
                cpa16(&Vs[0][vrow][(vch + q) * 8], V + (size_t)vrow * HW + j0 + (vch + q) * 8);
                cpa16(&Xs[0][vrow][(vch + q) * 8], X + (size_t)vrow * CH + c0 + (vch + q) * 8);
            }
            CP_COMMIT;
        }
        CP_WAIT0; __syncthreads();
        if (s < 127) {
            const int i0 = (s + 1) * 32, st2 = (s + 1) & 1;
#pragma unroll
            for (int q = 0; q < 2; q++) {
                cpa16(&Vs[st2][vrow][(vch + q) * 8],
                      V + (size_t)(i0 + vrow) * HW + j0 + (vch + q) * 8);
                cpa16(&Xs[st2][vrow][(vch + q) * 8],
                      X + (size_t)(i0 + vrow) * CH + c0 + (vch + q) * 8);
            }
        }
        CP_COMMIT;
        const int st = s & 1;
#pragma unroll
        for (int kk = 0; kk < 2; kk++) {
            uint32_t a[4][4], b[4][2];
#pragma unroll
            for (int mf = 0; mf < 4; mf++) {
                const int row = kk * 16 + (lane & 7) + (lane >> 4) * 8;
                const int col = wm * 64 + mf * 16 + ((lane >> 3) & 1) * 8;
                ldsm4t(a[mf], cvta_s(&Vs[st][row][col]));
            }
#pragma unroll
            for (int np = 0; np < 2; np++) {
                const int row = kk * 16 + (lane & 7) + ((lane >> 3) & 1) * 8;
                const int col = wn * 32 + np * 16 + (lane >> 4) * 8;
                uint32_t r[4];
                ldsm4t(r, cvta_s(&Xs[st][row][col]));
                b[2 * np][0] = r[0]; b[2 * np][1] = r[1];
                b[2 * np + 1][0] = r[2]; b[2 * np + 1][1] = r[3];
            }
#pragma unroll
            for (int mf = 0; mf < 4; mf++)
#pragma unroll
                for (int nf = 0; nf < 4; nf++) mma16816(acc[mf][nf], a[mf], b[nf]);
        }
        __syncthreads();
    }
#pragma unroll
    for (int mf = 0; mf < 4; mf++) {
        const int j = j0 + wm * 64 + mf * 16 + (lane >> 2);
#pragma unroll
        for (int nf = 0; nf < 4; nf++) {
            const int cc = wn * 32 + nf * 8 + (lane & 3) * 2;
            const size_t b0 = ((size_t)bat * HW + j) * CH + c0 + cc;
            float2 xv = *(const float2*)&x_in[b0];
            float2 o;
            o.x = acc[mf][nf][0] + xv.x + cs_s[cc];
            o.y = acc[mf][nf][1] + xv.y + cs_s[cc + 1];
            *(float2*)&out[b0] = o;
            const size_t b1 = ((size_t)bat * HW + j + 8) * CH + c0 + cc;
            float2 xv2 = *(const float2*)&x_in[b1];
            float2 o2;
            o2.x = acc[mf][nf][2] + xv2.x + cs_s[cc];
            o2.y = acc[mf][nf][3] + xv2.y + cs_s[cc + 1];
            *(float2*)&out[b1] = o2;
        }
    }
}

// ---------------------------------------------------------------------------
extern "C" void kernel_launch(void* const* d_in, const int* in_sizes, int n_in,
                              void* d_out, int out_size) {
    (void)in_sizes; (void)n_in; (void)out_size;
    const float* x   = (const float*)d_in[0];
    const float* g   = (const float*)d_in[1];
    const float* Wx1 = (const float*)d_in[2];
    const float* bx1 = (const float*)d_in[3];
    const float* Wx2 = (const float*)d_in[4];
    const float* bx2 = (const float*)d_in[5];
    const float* Wx3 = (const float*)d_in[6];
    const float* bx3 = (const float*)d_in[7];
    const float* Wg1 = (const float*)d_in[8];
    const float* bg1 = (const float*)d_in[9];
    const float* Wg2 = (const float*)d_in[10];
    const float* bg2 = (const float*)d_in[11];
    float* out = (float*)d_out;

    dim3 pg(CH / 64, (BATCH * HW) / 64);
    proj_gemm<<<pg, 256>>>(x, Wx1, bx1, 0);
    proj_gemm<<<pg, 256>>>(x, Wx2, bx2, 1);
    proj_gemm<<<pg, 256>>>(x, Wx3, bx3, 2);
    proj_gemm<<<pg, 256>>>(g, Wg1, bg1, 3);
    proj_gemm<<<pg, 256>>>(g, Wg2, bg2, 4);

    dim3 sg(HW / 128, HW / 128);   // 32x32
    for (int b = 0; b < BATCH; b++) {
        score_mma<<<sg, 256>>>(b, 1, 0, 0);   // Sx = xw2 @ xw1^T
        score_mma<<<sg, 256>>>(b, 4, 3, 1);   // Sg = gw2 @ gw1^T
    }

    row_stats_kernel<<<BATCH * HW, 256>>>();
    fold_kernel<<<128, 256>>>();
    colsum_reduce<<<BATCH, 256>>>();

    dim3 og(CH / 128, HW / 128, BATCH);   // (2, 32, 4)
    out_mma<<<og, 256>>>(x, out);
}

// round 9
// speedup vs baseline: 5.2643x; 1.2654x over previous
#include <cuda_runtime.h>
#include <cuda_bf16.h>
#include <cstdint>

#define BATCH 4
#define HW    4096
#define CH    256
#define PROJ_SZ (BATCH * HW * CH)

// ---- device scratch (EXACT R3 set) ----
__device__ __nv_bfloat16 g_Pb[5u * PROJ_SZ];                 // projections bf16
__device__ float         g_X3[PROJ_SZ];                      // xw3 fp32
__device__ __nv_bfloat16 g_X3p[PROJ_SZ];                     // invZ2-folded xw3 bf16
__device__ __nv_bfloat16 g_Sx[(size_t)BATCH * HW * HW];
__device__ __nv_bfloat16 g_Sg[(size_t)BATCH * HW * HW];
__device__ __nv_bfloat16 g_V[(size_t)BATCH * HW * HW];
__device__ float g_invZ2[BATCH * HW];
__device__ float g_colpart[128 * CH];
__device__ float g_colsum[BATCH * CH];

// ---- mma helpers (identical to R3) ----
__device__ __forceinline__ uint32_t cvta_s(const void* p) {
    return (uint32_t)__cvta_generic_to_shared(p);
}
__device__ __forceinline__ void ldsm4(uint32_t* r, uint32_t a) {
    asm volatile("ldmatrix.sync.aligned.m8n8.x4.shared.b16 {%0,%1,%2,%3},[%4];"
                 : "=r"(r[0]), "=r"(r[1]), "=r"(r[2]), "=r"(r[3]) : "r"(a));
}
__device__ __forceinline__ void ldsm4t(uint32_t* r, uint32_t a) {
    asm volatile("ldmatrix.sync.aligned.m8n8.x4.trans.shared.b16 {%0,%1,%2,%3},[%4];"
                 : "=r"(r[0]), "=r"(r[1]), "=r"(r[2]), "=r"(r[3]) : "r"(a));
}
__device__ __forceinline__ void mma16816(float* c, const uint32_t* a, const uint32_t* b) {
    asm volatile("mma.sync.aligned.m16n8k16.row.col.f32.bf16.bf16.f32 "
                 "{%0,%1,%2,%3},{%4,%5,%6,%7},{%8,%9},{%0,%1,%2,%3};"
                 : "+f"(c[0]), "+f"(c[1]), "+f"(c[2]), "+f"(c[3])
                 : "r"(a[0]), "r"(a[1]), "r"(a[2]), "r"(a[3]), "r"(b[0]), "r"(b[1]));
}
__device__ __forceinline__ void cpa16(void* s, const void* g) {
    asm volatile("cp.async.cg.shared.global [%0],[%1],16;" :: "r"(cvta_s(s)), "l"(g));
}
#define CP_COMMIT asm volatile("cp.async.commit_group;")
#define CP_WAIT0  asm volatile("cp.async.wait_group 0;")

// pack float4 -> 4 bf16 (as uint2) in registers
__device__ __forceinline__ uint2 f4b(float4 v) {
    __nv_bfloat162 lo, hi;
    lo.x = __float2bfloat16(v.x); lo.y = __float2bfloat16(v.y);
    hi.x = __float2bfloat16(v.z); hi.y = __float2bfloat16(v.w);
    uint2 r;
    r.x = *(uint32_t*)&lo;
    r.y = *(uint32_t*)&hi;
    return r;
}

// ---------------------------------------------------------------------------
// NEW: proj mma reading fp32 inputs directly.
// C[16384,256] = A[16384,256] @ W[256,256] + bias -> g_Pb[which] (bf16),
// and (wantf32) also fp32 -> g_X3.  Tile 128x128x32, 8 warps (2m x 4n).
// A-fragments: score_mma's ldsm4 path.  B-fragments: out_mma's ldsm4t path
// on a [k][n] tile staged coalesced from W's k-major rows.
// ---------------------------------------------------------------------------
__global__ __launch_bounds__(256) void proj_mma_f32(
    const float* __restrict__ A, const float* __restrict__ W,
    const float* __restrict__ bias, int which, int wantf32)
{
    __shared__ __align__(16) __nv_bfloat16 As[2][128][40];
    __shared__ __align__(16) __nv_bfloat16 Ws[2][32][136];
    const int tid = threadIdx.x, lane = tid & 31, wid = tid >> 5;
    const int wm = wid & 1, wn = wid >> 1;
    const int m0 = blockIdx.y * 128, n0 = blockIdx.x * 128;
    __nv_bfloat16* Dst = g_Pb + (size_t)which * PROJ_SZ;

    // staging assignments
    const int arow = tid >> 1;          // 0..127
    const int ak   = (tid & 1) * 16;    // 0 | 16
    const int wrow = tid >> 3;          // 0..31
    const int wn16 = (tid & 7) * 16;    // 0..112

    float4 ra0, ra1, ra2, ra3, rw0, rw1, rw2, rw3;

    // load stage 0 into registers
    {
        const float* ap = A + (size_t)(m0 + arow) * CH + ak;
        ra0 = *(const float4*)(ap + 0);  ra1 = *(const float4*)(ap + 4);
        ra2 = *(const float4*)(ap + 8);  ra3 = *(const float4*)(ap + 12);
        const float* wp = W + (size_t)wrow * CH + n0 + wn16;
        rw0 = *(const float4*)(wp + 0);  rw1 = *(const float4*)(wp + 4);
        rw2 = *(const float4*)(wp + 8);  rw3 = *(const float4*)(wp + 12);
    }
    // store stage 0
    *(uint2*)&As[0][arow][ak + 0]  = f4b(ra0);
    *(uint2*)&As[0][arow][ak + 4]  = f4b(ra1);
    *(uint2*)&As[0][arow][ak + 8]  = f4b(ra2);
    *(uint2*)&As[0][arow][ak + 12] = f4b(ra3);
    *(uint2*)&Ws[0][wrow][wn16 + 0]  = f4b(rw0);
    *(uint2*)&Ws[0][wrow][wn16 + 4]  = f4b(rw1);
    *(uint2*)&Ws[0][wrow][wn16 + 8]  = f4b(rw2);
    *(uint2*)&Ws[0][wrow][wn16 + 12] = f4b(rw3);
    __syncthreads();

    float acc[4][4][4] = {};
#pragma unroll 1
    for (int s = 0; s < 8; s++) {
        if (s < 7) {
            const int k0 = (s + 1) * 32;
            const float* ap = A + (size_t)(m0 + arow) * CH + k0 + ak;
            ra0 = *(const float4*)(ap + 0);  ra1 = *(const float4*)(ap + 4);
            ra2 = *(const float4*)(ap + 8);  ra3 = *(const float4*)(ap + 12);
            const float* wp = W + (size_t)(k0 + wrow) * CH + n0 + wn16;
            rw0 = *(const float4*)(wp + 0);  rw1 = *(const float4*)(wp + 4);
            rw2 = *(const float4*)(wp + 8);  rw3 = *(const float4*)(wp + 12);
        }
        const int st = s & 1;
#pragma unroll
        for (int kk = 0; kk < 2; kk++) {
            uint32_t a[4][4], b[4][2];
#pragma unroll
            for (int mf = 0; mf < 4; mf++) {
                const int row = wm * 64 + mf * 16 + (lane & 15);
                const int ko = kk * 16 + (lane >> 4) * 8;
                ldsm4(a[mf], cvta_s(&As[st][row][ko]));
            }
#pragma unroll
            for (int np = 0; np < 2; np++) {
                const int row = kk * 16 + (lane & 7) + ((lane >> 3) & 1) * 8;
                const int col = wn * 32 + np * 16 + (lane >> 4) * 8;
                uint32_t r[4];
                ldsm4t(r, cvta_s(&Ws[st][row][col]));
                b[2 * np][0] = r[0]; b[2 * np][1] = r[1];
                b[2 * np + 1][0] = r[2]; b[2 * np + 1][1] = r[3];
            }
#pragma unroll
            for (int mf = 0; mf < 4; mf++)
#pragma unroll
                for (int nf = 0; nf < 4; nf++) mma16816(acc[mf][nf], a[mf], b[nf]);
        }
        __syncthreads();
        if (s < 7) {
            const int st2 = (s + 1) & 1;
            *(uint2*)&As[st2][arow][ak + 0]  = f4b(ra0);
            *(uint2*)&As[st2][arow][ak + 4]  = f4b(ra1);
            *(uint2*)&As[st2][arow][ak + 8]  = f4b(ra2);
            *(uint2*)&As[st2][arow][ak + 12] = f4b(ra3);
            *(uint2*)&Ws[st2][wrow][wn16 + 0]  = f4b(rw0);
            *(uint2*)&Ws[st2][wrow][wn16 + 4]  = f4b(rw1);
            *(uint2*)&Ws[st2][wrow][wn16 + 8]  = f4b(rw2);
            *(uint2*)&Ws[st2][wrow][wn16 + 12] = f4b(rw3);
            __syncthreads();
        }
    }

    const int mm0 = m0 + wm * 64, nn0 = n0 + wn * 32;
#pragma unroll
    for (int mf = 0; mf < 4; mf++) {
        const int r0 = mm0 + mf * 16 + (lane >> 2);
#pragma unroll
        for (int nf = 0; nf < 4; nf++) {
            const int col = nn0 + nf * 8 + (lane & 3) * 2;
            const float b0 = bias[col], b1 = bias[col + 1];
            const float f0 = acc[mf][nf][0] + b0, f1 = acc[mf][nf][1] + b1;
            const float f2 = acc[mf][nf][2] + b0, f3 = acc[mf][nf][3] + b1;
            __nv_bfloat162 v0, v1;
            v0.x = __float2bfloat16(f0); v0.y = __float2bfloat16(f1);
            v1.x = __float2bfloat16(f2); v1.y = __float2bfloat16(f3);
            *(__nv_bfloat162*)&Dst[(size_t)r0 * CH + col] = v0;
            *(__nv_bfloat162*)&Dst[(size_t)(r0 + 8) * CH + col] = v1;
            if (wantf32) {
                float2 w0; w0.x = f0; w0.y = f1;
                float2 w1; w1.x = f2; w1.y = f3;
                *(float2*)&g_X3[(size_t)r0 * CH + col] = w0;
                *(float2*)&g_X3[(size_t)(r0 + 8) * CH + col] = w1;
            }
        }
    }
}

// ---------------------------------------------------------------------------
// score mma — VERBATIM R3 (per-batch launch)
// ---------------------------------------------------------------------------
__global__ __launch_bounds__(256) void score_mma(int bat, int aw, int bw, int dest) {
    __shared__ __align__(16) __nv_bfloat16 As[2][128][40];
    __shared__ __align__(16) __nv_bfloat16 Bs[2][128][40];
    const __nv_bfloat16* A  = g_Pb + (size_t)aw * PROJ_SZ + (size_t)bat * HW * CH
                              + (size_t)blockIdx.y * 128 * CH;
    const __nv_bfloat16* Bm = g_Pb + (size_t)bw * PROJ_SZ + (size_t)bat * HW * CH
                              + (size_t)blockIdx.x * 128 * CH;
    __nv_bfloat16* Dst = (dest ? g_Sg : g_Sx) + (size_t)bat * HW * HW;
    const int tid = threadIdx.x, lane = tid & 31, wid = tid >> 5;
    const int wm = wid & 1, wn = wid >> 1;
    const int lrow = tid >> 1, lch = (tid & 1) * 2;

    float acc[4][4][4] = {};
#pragma unroll 1
    for (int s = 0; s < 8; s++) {
        if (s == 0) {
#pragma unroll
            for (int q = 0; q < 2; q++) {
                cpa16(&As[0][lrow][(lch + q) * 8], A + (size_t)lrow * CH + (lch + q) * 8);
                cpa16(&Bs[0][lrow][(lch + q) * 8], Bm + (size_t)lrow * CH + (lch + q) * 8);
            }
            CP_COMMIT;
        }
        CP_WAIT0; __syncthreads();
        if (s < 7) {
            const int k0 = (s + 1) * 32, st2 = (s + 1) & 1;
#pragma unroll
            for (int q = 0; q < 2; q++) {
                cpa16(&As[st2][lrow][(lch + q) * 8], A + (size_t)lrow * CH + k0 + (lch + q) * 8);
                cpa16(&Bs[st2][lrow][(lch + q) * 8], Bm + (size_t)lrow * CH + k0 + (lch + q) * 8);
            }
        }
        CP_COMMIT;
        const int st = s & 1;
#pragma unroll
        for (int kk = 0; kk < 2; kk++) {
            uint32_t a[4][4], b[4][2];
#pragma unroll
            for (int mf = 0; mf < 4; mf++) {
                const int row = wm * 64 + mf * 16 + (lane & 15);
                const int ko = kk * 16 + (lane >> 4) * 8;
                ldsm4(a[mf], cvta_s(&As[st][row][ko]));
            }
#pragma unroll
            for (int np = 0; np < 2; np++) {
                const int row = wn * 32 + np * 16 + (lane & 7) + (lane >> 4) * 8;
                const int ko = kk * 16 + ((lane >> 3) & 1) * 8;
                uint32_t r[4];
                ldsm4(r, cvta_s(&Bs[st][row][ko]));
                b[2 * np][0] = r[0]; b[2 * np][1] = r[1];
                b[2 * np + 1][0] = r[2]; b[2 * np + 1][1] = r[3];
            }
#pragma unroll
            for (int mf = 0; mf < 4; mf++)
#pragma unroll
                for (int nf = 0; nf < 4; nf++) mma16816(acc[mf][nf], a[mf], b[nf]);
        }
        __syncthreads();
    }
    const int m0 = blockIdx.y * 128 + wm * 64, n0 = blockIdx.x * 128 + wn * 32;
#pragma unroll
    for (int mf = 0; mf < 4; mf++) {
        const int r0 = m0 + mf * 16 + (lane >> 2);
#pragma unroll
        for (int nf = 0; nf < 4; nf++) {
            const int col = n0 + nf * 8 + (lane & 3) * 2;
            __nv_bfloat162 v0, v1;
            v0.x = __float2bfloat16(acc[mf][nf][0]); v0.y = __float2bfloat16(acc[mf][nf][1]);
            v1.x = __float2bfloat16(acc[mf][nf][2]); v1.y = __float2bfloat16(acc[mf][nf][3]);
            *(__nv_bfloat162*)&Dst[(size_t)r0 * HW + col] = v0;
            *(__nv_bfloat162*)&Dst[(size_t)(r0 + 8) * HW + col] = v1;
        }
    }
}

// ---------------------------------------------------------------------------
// row stats — VERBATIM R3 (max-based)
// ---------------------------------------------------------------------------
__device__ __forceinline__ float blk_max(float v, float* red) {
    int tid = threadIdx.x;
    red[tid] = v; __syncthreads();
    for (int s = 128; s > 0; s >>= 1) {
        if (tid < s) red[tid] = fmaxf(red[tid], red[tid + s]);
        __syncthreads();
    }
    float r = red[0]; __syncthreads();
    return r;
}
__device__ __forceinline__ float blk_sum(float v, float* red) {
    int tid = threadIdx.x;
    red[tid] = v; __syncthreads();
    for (int s = 128; s > 0; s >>= 1) {
        if (tid < s) red[tid] += red[tid + s];
        __syncthreads();
    }
    float r = red[0]; __syncthreads();
    return r;
}

__global__ void row_stats_kernel() {
    __shared__ float sx[HW];
    __shared__ float sg[HW];
    __shared__ float red[256];
    const int row = blockIdx.x;
    const int tid = threadIdx.x;
    const __nv_bfloat16* px = g_Sx + (size_t)row * HW;
    const __nv_bfloat16* pg = g_Sg + (size_t)row * HW;

    for (int t = tid; t < HW / 4; t += 256) {
        __nv_bfloat162 x0 = *(const __nv_bfloat162*)&px[t * 4];
        __nv_bfloat162 x1 = *(const __nv_bfloat162*)&px[t * 4 + 2];
        __nv_bfloat162 g0 = *(const __nv_bfloat162*)&pg[t * 4];
        __nv_bfloat162 g1 = *(const __nv_bfloat162*)&pg[t * 4 + 2];
        sx[t * 4 + 0] = __bfloat162float(x0.x); sx[t * 4 + 1] = __bfloat162float(x0.y);
        sx[t * 4 + 2] = __bfloat162float(x1.x); sx[t * 4 + 3] = __bfloat162float(x1.y);
        sg[t * 4 + 0] = __bfloat162float(g0.x); sg[t * 4 + 1] = __bfloat162float(g0.y);
        sg[t * 4 + 2] = __bfloat162float(g1.x); sg[t * 4 + 3] = __bfloat162float(g1.y);
    }
    __syncthreads();

    float v = -1e30f;
    for (int t = tid; t < HW; t += 256) v = fmaxf(v, sx[t]);
    const float mx = blk_max(v, red);
    float s = 0.f;
    for (int t = tid; t < HW; t += 256) s += __expf(sx[t] - mx);
    const float Zx = blk_sum(s, red);

    v = -1e30f;
    for (int t = tid; t < HW; t += 256) v = fmaxf(v, sg[t]);
    const float mg = blk_max(v, red);
    s = 0.f;
    for (int t = tid; t < HW; t += 256) s += __expf(sg[t] - mg);
    const float Zg = blk_sum(s, red);

    v = -1e30f;
    for (int t = tid; t < HW; t += 256) v = fmaxf(v, sx[t] + sg[t]);
    const float m2 = blk_max(v, red);

    const float L = mx + mg + __logf(Zx) + __logf(Zg);
    const float pmax = __expf(m2 - L);

    __nv_bfloat16* vo = g_V + (size_t)row * HW;
    s = 0.f;
    for (int t = tid; t < HW; t += 256) {
        const float p = __expf(sx[t] + sg[t] - L);
        const float tt = p - pmax;   // in [-pmax, 0]
        const float vv = tt * (1.f + tt * (0.5f + tt * (0.16666667f + tt * 0.04166667f)));
        s += vv;
        vo[t] = __float2bfloat16(vv);
    }
    const float Z2 = (float)HW + blk_sum(s, red);
    if (tid == 0) g_invZ2[row] = 1.f / Z2;
}

// ---------------------------------------------------------------------------
// fold — VERBATIM R3 (reads fp32 g_X3)
// ---------------------------------------------------------------------------
__global__ void fold_kernel() {
    const int blk = blockIdx.x;              // 0..127
    const int bat = blk >> 5;
    const int i0 = (blk & 31) * 128;
    const int c = threadIdx.x;               // 0..255
    const float* X = g_X3 + ((size_t)bat * HW + i0) * CH;
    __nv_bfloat16* P = g_X3p + ((size_t)bat * HW + i0) * CH;
    const float* iz = g_invZ2 + bat * HW + i0;
    float s = 0.f;
#pragma unroll 4
    for (int r = 0; r < 128; r++) {
        const float val = X[(size_t)r * CH + c] * iz[r];
        s += val;
        P[(size_t)r * CH + c] = __float2bfloat16(val);
    }
    g_colpart[blk * CH + c] = s;
}
__global__ void colsum_reduce() {
    const int bat = blockIdx.x, c = threadIdx.x;
    float s = 0.f;
    for (int k = 0; k < 32; k++) s += g_colpart[(bat * 32 + k) * CH + c];
    g_colsum[bat * CH + c] = s;
}

// ---------------------------------------------------------------------------
// out mma — VERBATIM R3
// ---------------------------------------------------------------------------
__global__ __launch_bounds__(256) void out_mma(const float* __restrict__ x_in,
                                               float* __restrict__ out) {
    __shared__ __align__(16) __nv_bfloat16 Vs[2][32][136];
    __shared__ __align__(16) __nv_bfloat16 Xs[2][32][136];
    __shared__ float cs_s[128];
    const int bat = blockIdx.z;
    const int j0 = blockIdx.y * 128, c0 = blockIdx.x * 128;
    const __nv_bfloat16* V = g_V + (size_t)bat * HW * HW;      // [i][j]
    const __nv_bfloat16* X = g_X3p + (size_t)bat * HW * CH;    // [i][c]
    const int tid = threadIdx.x, lane = tid & 31, wid = tid >> 5;
    const int wm = wid & 1, wn = wid >> 1;
    const int vrow = tid >> 3;          // 0..31
    const int vch = (tid & 7) * 2;

    if (tid < 128) cs_s[tid] = g_colsum[bat * CH + c0 + tid];

    float acc[4][4][4] = {};

#pragma unroll 1
    for (int s = 0; s < 128; s++) {
        if (s == 0) {
#pragma unroll
            for (int q = 0; q < 2; q++) {
                cpa16(&Vs[0][vrow][(vch + q) * 8], V + (size_t)vrow * HW + j0 + (vch + q) * 8);
                cpa16(&Xs[0][vrow][(vch + q) * 8], X + (size_t)vrow * CH + c0 + (vch + q) * 8);
            }
            CP_COMMIT;
        }
        CP_WAIT0; __syncthreads();
        if (s < 127) {
            const int i0 = (s + 1) * 32, st2 = (s + 1) & 1;
#pragma unroll
            for (int q = 0; q < 2; q++) {
                cpa16(&Vs[st2][vrow][(vch + q) * 8],
                      V + (size_t)(i0 + vrow) * HW + j0 + (vch + q) * 8);
                cpa16(&Xs[st2][vrow][(vch + q) * 8],
                      X + (size_t)(i0 + vrow) * CH + c0 + (vch + q) * 8);
            }
        }
        CP_COMMIT;
        const int st = s & 1;
#pragma unroll
        for (int kk = 0; kk < 2; kk++) {
            uint32_t a[4][4], b[4][2];
#pragma unroll
            for (int mf = 0; mf < 4; mf++) {
                const int row = kk * 16 + (lane & 7) + (lane >> 4) * 8;
                const int col = wm * 64 + mf * 16 + ((lane >> 3) & 1) * 8;
                ldsm4t(a[mf], cvta_s(&Vs[st][row][col]));
            }
#pragma unroll
            for (int np = 0; np < 2; np++) {
                const int row = kk * 16 + (lane & 7) + ((lane >> 3) & 1) * 8;
                const int col = wn * 32 + np * 16 + (lane >> 4) * 8;
                uint32_t r[4];
                ldsm4t(r, cvta_s(&Xs[st][row][col]));
                b[2 * np][0] = r[0]; b[2 * np][1] = r[1];
                b[2 * np + 1][0] = r[2]; b[2 * np + 1][1] = r[3];
            }
#pragma unroll
            for (int mf = 0; mf < 4; mf++)
#pragma unroll
                for (int nf = 0; nf < 4; nf++) mma16816(acc[mf][nf], a[mf], b[nf]);
        }
        __syncthreads();
    }
#pragma unroll
    for (int mf = 0; mf < 4; mf++) {
        const int j = j0 + wm * 64 + mf * 16 + (lane >> 2);
#pragma unroll
        for (int nf = 0; nf < 4; nf++) {
            const int cc = wn * 32 + nf * 8 + (lane & 3) * 2;
            const size_t b0 = ((size_t)bat * HW + j) * CH + c0 + cc;
            float2 xv = *(const float2*)&x_in[b0];
            float2 o;
            o.x = acc[mf][nf][0] + xv.x + cs_s[cc];
            o.y = acc[mf][nf][1] + xv.y + cs_s[cc + 1];
            *(float2*)&out[b0] = o;
            const size_t b1 = ((size_t)bat * HW + j + 8) * CH + c0 + cc;
            float2 xv2 = *(const float2*)&x_in[b1];
            float2 o2;
            o2.x = acc[mf][nf][2] + xv2.x + cs_s[cc];
            o2.y = acc[mf][nf][3] + xv2.y + cs_s[cc + 1];
            *(float2*)&out[b1] = o2;
        }
    }
}

// ---------------------------------------------------------------------------
extern "C" void kernel_launch(void* const* d_in, const int* in_sizes, int n_in,
                              void* d_out, int out_size) {
    (void)in_sizes; (void)n_in; (void)out_size;
    const float* x   = (const float*)d_in[0];
    const float* g   = (const float*)d_in[1];
    const float* Wx1 = (const float*)d_in[2];
    const float* bx1 = (const float*)d_in[3];
    const float* Wx2 = (const float*)d_in[4];
    const float* bx2 = (const float*)d_in[5];
    const float* Wx3 = (const float*)d_in[6];
    const float* bx3 = (const float*)d_in[7];
    const float* Wg1 = (const float*)d_in[8];
    const float* bg1 = (const float*)d_in[9];
    const float* Wg2 = (const float*)d_in[10];
    const float* bg2 = (const float*)d_in[11];
    float* out = (float*)d_out;

    dim3 pg(CH / 128, (BATCH * HW) / 128);   // (2, 128)
    proj_mma_f32<<<pg, 256>>>(x, Wx1, bx1, 0, 0);
    proj_mma_f32<<<pg, 256>>>(x, Wx2, bx2, 1, 0);
    proj_mma_f32<<<pg, 256>>>(x, Wx3, bx3, 2, 1);
    proj_mma_f32<<<pg, 256>>>(g, Wg1, bg1, 3, 0);
    proj_mma_f32<<<pg, 256>>>(g, Wg2, bg2, 4, 0);

    dim3 sg(HW / 128, HW / 128);             // per-batch, like R3
    for (int b = 0; b < BATCH; b++) {
        score_mma<<<sg, 256>>>(b, 1, 0, 0);  // Sx = xw2 @ xw1^T
        score_mma<<<sg, 256>>>(b, 4, 3, 1);  // Sg = gw2 @ gw1^T
    }

    row_stats_kernel<<<BATCH * HW, 256>>>();
    fold_kernel<<<128, 256>>>();
    colsum_reduce<<<BATCH, 256>>>();

    out_mma<<<dim3(CH / 128, HW / 128, BATCH), 256>>>(x, out);
}

// round 10
// speedup vs baseline: 6.1869x; 1.1753x over previous
#include <cuda_runtime.h>
#include <cuda_bf16.h>
#include <cstdint>

#define BATCH 4
#define HW    4096
#define CH    256
#define PROJ_SZ (BATCH * HW * CH)

// ---- device scratch ----
__device__ __nv_bfloat16 g_Pb[5u * PROJ_SZ];                 // projections bf16
__device__ float         g_X3[PROJ_SZ];                      // xw3 fp32
__device__ __nv_bfloat16 g_X3p[PROJ_SZ];                     // invZ2-folded xw3 bf16
__device__ __nv_bfloat16 g_Sx[(size_t)BATCH * HW * HW];
__device__ __nv_bfloat16 g_Sg[(size_t)BATCH * HW * HW];
__device__ __nv_bfloat16 g_V[(size_t)BATCH * HW * HW];
__device__ float g_invZ2[BATCH * HW];
__device__ float g_colpart[128 * CH];
__device__ float g_colsum[BATCH * CH];

// ---- mma helpers ----
__device__ __forceinline__ uint32_t cvta_s(const void* p) {
    return (uint32_t)__cvta_generic_to_shared(p);
}
__device__ __forceinline__ void ldsm4(uint32_t* r, uint32_t a) {
    asm volatile("ldmatrix.sync.aligned.m8n8.x4.shared.b16 {%0,%1,%2,%3},[%4];"
                 : "=r"(r[0]), "=r"(r[1]), "=r"(r[2]), "=r"(r[3]) : "r"(a));
}
__device__ __forceinline__ void ldsm4t(uint32_t* r, uint32_t a) {
    asm volatile("ldmatrix.sync.aligned.m8n8.x4.trans.shared.b16 {%0,%1,%2,%3},[%4];"
                 : "=r"(r[0]), "=r"(r[1]), "=r"(r[2]), "=r"(r[3]) : "r"(a));
}
__device__ __forceinline__ void mma16816(float* c, const uint32_t* a, const uint32_t* b) {
    asm volatile("mma.sync.aligned.m16n8k16.row.col.f32.bf16.bf16.f32 "
                 "{%0,%1,%2,%3},{%4,%5,%6,%7},{%8,%9},{%0,%1,%2,%3};"
                 : "+f"(c[0]), "+f"(c[1]), "+f"(c[2]), "+f"(c[3])
                 : "r"(a[0]), "r"(a[1]), "r"(a[2]), "r"(a[3]), "r"(b[0]), "r"(b[1]));
}
__device__ __forceinline__ void cpa16(void* s, const void* g) {
    asm volatile("cp.async.cg.shared.global [%0],[%1],16;" :: "r"(cvta_s(s)), "l"(g));
}
#define CP_COMMIT asm volatile("cp.async.commit_group;")
#define CP_WAIT0  asm volatile("cp.async.wait_group 0;")

// pack float4 -> 4 bf16 (as uint2) in registers
__device__ __forceinline__ uint2 f4b(float4 v) {
    __nv_bfloat162 lo, hi;
    lo.x = __float2bfloat16(v.x); lo.y = __float2bfloat16(v.y);
    hi.x = __float2bfloat16(v.z); hi.y = __float2bfloat16(v.w);
    uint2 r;
    r.x = *(uint32_t*)&lo;
    r.y = *(uint32_t*)&hi;
    return r;
}

// ---------------------------------------------------------------------------
// proj mma (merged z=5): same body as R9-proven proj_mma_f32; weight/bias
// selected by scalar if/else on blockIdx.z (no arrays -> no local memory).
// ---------------------------------------------------------------------------
__global__ __launch_bounds__(256) void proj_mma_f32(
    const float* __restrict__ x_in, const float* __restrict__ g_in,
    const float* __restrict__ Wx1, const float* __restrict__ bx1,
    const float* __restrict__ Wx2, const float* __restrict__ bx2,
    const float* __restrict__ Wx3, const float* __restrict__ bx3,
    const float* __restrict__ Wg1, const float* __restrict__ bg1,
    const float* __restrict__ Wg2, const float* __restrict__ bg2)
{
    __shared__ __align__(16) __nv_bfloat16 As[2][128][40];
    __shared__ __align__(16) __nv_bfloat16 Ws[2][32][136];
    const int z = blockIdx.z;
    const float* A; const float* W; const float* bias; int wantf32;
    if (z == 0)      { A = x_in; W = Wx1; bias = bx1; wantf32 = 0; }
    else if (z == 1) { A = x_in; W = Wx2; bias = bx2; wantf32 = 0; }
    else if (z == 2) { A = x_in; W = Wx3; bias = bx3; wantf32 = 1; }
    else if (z == 3) { A = g_in; W = Wg1; bias = bg1; wantf32 = 0; }
    else             { A = g_in; W = Wg2; bias = bg2; wantf32 = 0; }

    const int tid = threadIdx.x, lane = tid & 31, wid = tid >> 5;
    const int wm = wid & 1, wn = wid >> 1;
    const int m0 = blockIdx.y * 128, n0 = blockIdx.x * 128;
    __nv_bfloat16* Dst = g_Pb + (size_t)z * PROJ_SZ;

    const int arow = tid >> 1;          // 0..127
    const int ak   = (tid & 1) * 16;    // 0 | 16
    const int wrow = tid >> 3;          // 0..31
    const int wn16 = (tid & 7) * 16;    // 0..112

    float4 ra0, ra1, ra2, ra3, rw0, rw1, rw2, rw3;

    {
        const float* ap = A + (size_t)(m0 + arow) * CH + ak;
        ra0 = *(const float4*)(ap + 0);  ra1 = *(const float4*)(ap + 4);
        ra2 = *(const float4*)(ap + 8);  ra3 = *(const float4*)(ap + 12);
        const float* wp = W + (size_t)wrow * CH + n0 + wn16;
        rw0 = *(const float4*)(wp + 0);  rw1 = *(const float4*)(wp + 4);
        rw2 = *(const float4*)(wp + 8);  rw3 = *(const float4*)(wp + 12);
    }
    *(uint2*)&As[0][arow][ak + 0]  = f4b(ra0);
    *(uint2*)&As[0][arow][ak + 4]  = f4b(ra1);
    *(uint2*)&As[0][arow][ak + 8]  = f4b(ra2);
    *(uint2*)&As[0][arow][ak + 12] = f4b(ra3);
    *(uint2*)&Ws[0][wrow][wn16 + 0]  = f4b(rw0);
    *(uint2*)&Ws[0][wrow][wn16 + 4]  = f4b(rw1);
    *(uint2*)&Ws[0][wrow][wn16 + 8]  = f4b(rw2);
    *(uint2*)&Ws[0][wrow][wn16 + 12] = f4b(rw3);
    __syncthreads();

    float acc[4][4][4] = {};
#pragma unroll 1
    for (int s = 0; s < 8; s++) {
        if (s < 7) {
            const int k0 = (s + 1) * 32;
            const float* ap = A + (size_t)(m0 + arow) * CH + k0 + ak;
            ra0 = *(const float4*)(ap + 0);  ra1 = *(const float4*)(ap + 4);
            ra2 = *(const float4*)(ap + 8);  ra3 = *(const float4*)(ap + 12);
            const float* wp = W + (size_t)(k0 + wrow) * CH + n0 + wn16;
            rw0 = *(const float4*)(wp + 0);  rw1 = *(const float4*)(wp + 4);
            rw2 = *(const float4*)(wp + 8);  rw3 = *(const float4*)(wp + 12);
        }
        const int st = s & 1;
#pragma unroll
        for (int kk = 0; kk < 2; kk++) {
            uint32_t a[4][4], b[4][2];
#pragma unroll
            for (int mf = 0; mf < 4; mf++) {
                const int row = wm * 64 + mf * 16 + (lane & 15);
                const int ko = kk * 16 + (lane >> 4) * 8;
                ldsm4(a[mf], cvta_s(&As[st][row][ko]));
            }
#pragma unroll
            for (int np = 0; np < 2; np++) {
                const int row = kk * 16 + (lane & 7) + ((lane >> 3) & 1) * 8;
                const int col = wn * 32 + np * 16 + (lane >> 4) * 8;
                uint32_t r[4];
                ldsm4t(r, cvta_s(&Ws[st][row][col]));
                b[2 * np][0] = r[0]; b[2 * np][1] = r[1];
                b[2 * np + 1][0] = r[2]; b[2 * np + 1][1] = r[3];
            }
#pragma unroll
            for (int mf = 0; mf < 4; mf++)
#pragma unroll
                for (int nf = 0; nf < 4; nf++) mma16816(acc[mf][nf], a[mf], b[nf]);
        }
        __syncthreads();
        if (s < 7) {
            const int st2 = (s + 1) & 1;
            *(uint2*)&As[st2][arow][ak + 0]  = f4b(ra0);
            *(uint2*)&As[st2][arow][ak + 4]  = f4b(ra1);
            *(uint2*)&As[st2][arow][ak + 8]  = f4b(ra2);
            *(uint2*)&As[st2][arow][ak + 12] = f4b(ra3);
            *(uint2*)&Ws[st2][wrow][wn16 + 0]  = f4b(rw0);
            *(uint2*)&Ws[st2][wrow][wn16 + 4]  = f4b(rw1);
            *(uint2*)&Ws[st2][wrow][wn16 + 8]  = f4b(rw2);
            *(uint2*)&Ws[st2][wrow][wn16 + 12] = f4b(rw3);
            __syncthreads();
        }
    }

    const int mm0 = m0 + wm * 64, nn0 = n0 + wn * 32;
#pragma unroll
    for (int mf = 0; mf < 4; mf++) {
        const int r0 = mm0 + mf * 16 + (lane >> 2);
#pragma unroll
        for (int nf = 0; nf < 4; nf++) {
            const int col = nn0 + nf * 8 + (lane & 3) * 2;
            const float b0 = bias[col], b1 = bias[col + 1];
            const float f0 = acc[mf][nf][0] + b0, f1 = acc[mf][nf][1] + b1;
            const float f2 = acc[mf][nf][2] + b0, f3 = acc[mf][nf][3] + b1;
            __nv_bfloat162 v0, v1;
            v0.x = __float2bfloat16(f0); v0.y = __float2bfloat16(f1);
            v1.x = __float2bfloat16(f2); v1.y = __float2bfloat16(f3);
            *(__nv_bfloat162*)&Dst[(size_t)r0 * CH + col] = v0;
            *(__nv_bfloat162*)&Dst[(size_t)(r0 + 8) * CH + col] = v1;
            if (wantf32) {
                float2 w0; w0.x = f0; w0.y = f1;
                float2 w1; w1.x = f2; w1.y = f3;
                *(float2*)&g_X3[(size_t)r0 * CH + col] = w0;
                *(float2*)&g_X3[(size_t)(r0 + 8) * CH + col] = w1;
            }
        }
    }
}

// ---------------------------------------------------------------------------
// score mma — VERBATIM R3/R9 (per-batch launch)
// ---------------------------------------------------------------------------
__global__ __launch_bounds__(256) void score_mma(int bat, int aw, int bw, int dest) {
    __shared__ __align__(16) __nv_bfloat16 As[2][128][40];
    __shared__ __align__(16) __nv_bfloat16 Bs[2][128][40];
    const __nv_bfloat16* A  = g_Pb + (size_t)aw * PROJ_SZ + (size_t)bat * HW * CH
                              + (size_t)blockIdx.y * 128 * CH;
    const __nv_bfloat16* Bm = g_Pb + (size_t)bw * PROJ_SZ + (size_t)bat * HW * CH
                              + (size_t)blockIdx.x * 128 * CH;
    __nv_bfloat16* Dst = (dest ? g_Sg : g_Sx) + (size_t)bat * HW * HW;
    const int tid = threadIdx.x, lane = tid & 31, wid = tid >> 5;
    const int wm = wid & 1, wn = wid >> 1;
    const int lrow = tid >> 1, lch = (tid & 1) * 2;

    float acc[4][4][4] = {};
#pragma unroll 1
    for (int s = 0; s < 8; s++) {
        if (s == 0) {
#pragma unroll
            for (int q = 0; q < 2; q++) {
                cpa16(&As[0][lrow][(lch + q) * 8], A + (size_t)lrow * CH + (lch + q) * 8);
                cpa16(&Bs[0][lrow][(lch + q) * 8], Bm + (size_t)lrow * CH + (lch + q) * 8);
            }
            CP_COMMIT;
        }
        CP_WAIT0; __syncthreads();
        if (s < 7) {
            const int k0 = (s + 1) * 32, st2 = (s + 1) & 1;
#pragma unroll
            for (int q = 0; q < 2; q++) {
                cpa16(&As[st2][lrow][(lch + q) * 8], A + (size_t)lrow * CH + k0 + (lch + q) * 8);
                cpa16(&Bs[st2][lrow][(lch + q) * 8], Bm + (size_t)lrow * CH + k0 + (lch + q) * 8);
            }
        }
        CP_COMMIT;
        const int st = s & 1;
#pragma unroll
        for (int kk = 0; kk < 2; kk++) {
            uint32_t a[4][4], b[4][2];
#pragma unroll
            for (int mf = 0; mf < 4; mf++) {
                const int row = wm * 64 + mf * 16 + (lane & 15);
                const int ko = kk * 16 + (lane >> 4) * 8;
                ldsm4(a[mf], cvta_s(&As[st][row][ko]));
            }
#pragma unroll
            for (int np = 0; np < 2; np++) {
                const int row = wn * 32 + np * 16 + (lane & 7) + (lane >> 4) * 8;
                const int ko = kk * 16 + ((lane >> 3) & 1) * 8;
                uint32_t r[4];
                ldsm4(r, cvta_s(&Bs[st][row][ko]));
                b[2 * np][0] = r[0]; b[2 * np][1] = r[1];
                b[2 * np + 1][0] = r[2]; b[2 * np + 1][1] = r[3];
            }
#pragma unroll
            for (int mf = 0; mf < 4; mf++)
#pragma unroll
                for (int nf = 0; nf < 4; nf++) mma16816(acc[mf][nf], a[mf], b[nf]);
        }
        __syncthreads();
    }
    const int m0 = blockIdx.y * 128 + wm * 64, n0 = blockIdx.x * 128 + wn * 32;
#pragma unroll
    for (int mf = 0; mf < 4; mf++) {
        const int r0 = m0 + mf * 16 + (lane >> 2);
#pragma unroll
        for (int nf = 0; nf < 4; nf++) {
            const int col = n0 + nf * 8 + (lane & 3) * 2;
            __nv_bfloat162 v0, v1;
            v0.x = __float2bfloat16(acc[mf][nf][0]); v0.y = __float2bfloat16(acc[mf][nf][1]);
            v1.x = __float2bfloat16(acc[mf][nf][2]); v1.y = __float2bfloat16(acc[mf][nf][3]);
            *(__nv_bfloat162*)&Dst[(size_t)r0 * HW + col] = v0;
            *(__nv_bfloat162*)&Dst[(size_t)(r0 + 8) * HW + col] = v1;
        }
    }
}

// ---------------------------------------------------------------------------
// row stats — max-free, 2 exps/elt, product cached in smem (16KB)
//   ex=exp(sx), eg=exp(sg): Zx=sum ex, Zg=sum eg (fp32-safe, scores ~N(0,1.6))
//   p = ex*eg/(Zx*Zg) in (0,1];  v = expm1(p) poly;  Z2 = HW + sum v
// ---------------------------------------------------------------------------
__device__ __forceinline__ float blk_sum(float v, float* red) {
    int tid = threadIdx.x;
    red[tid] = v; __syncthreads();
    for (int s = 128; s > 0; s >>= 1) {
        if (tid < s) red[tid] += red[tid + s];
        __syncthreads();
    }
    float r = red[0]; __syncthreads();
    return r;
}

__global__ void row_stats_kernel() {
    __shared__ float prod[HW];     // 16KB: exp(sx)*exp(sg)
    __shared__ float red[256];
    const int row = blockIdx.x;
    const int tid = threadIdx.x;
    const __nv_bfloat16* px = g_Sx + (size_t)row * HW;
    const __nv_bfloat16* pg = g_Sg + (size_t)row * HW;

    float s1 = 0.f, s2 = 0.f;
    for (int t = tid; t < HW / 4; t += 256) {
        __nv_bfloat162 x0 = *(const __nv_bfloat162*)&px[t * 4];
        __nv_bfloat162 x1 = *(const __nv_bfloat162*)&px[t * 4 + 2];
        __nv_bfloat162 g0 = *(const __nv_bfloat162*)&pg[t * 4];
        __nv_bfloat162 g1 = *(const __nv_bfloat162*)&pg[t * 4 + 2];
        const float ex0 = __expf(__bfloat162float(x0.x));
        const float ex1 = __expf(__bfloat162float(x0.y));
        const float ex2 = __expf(__bfloat162float(x1.x));
        const float ex3 = __expf(__bfloat162float(x1.y));
        const float eg0 = __expf(__bfloat162float(g0.x));
        const float eg1 = __expf(__bfloat162float(g0.y));
        const float eg2 = __expf(__bfloat162float(g1.x));
        const float eg3 = __expf(__bfloat162float(g1.y));
        s1 += ex0 + ex1 + ex2 + ex3;
        s2 += eg0 + eg1 + eg2 + eg3;
        prod[t * 4 + 0] = ex0 * eg0;
        prod[t * 4 + 1] = ex1 * eg1;
        prod[t * 4 + 2] = ex2 * eg2;
        prod[t * 4 + 3] = ex3 * eg3;
    }
    __syncthreads();
    const float Zx = blk_sum(s1, red);
    const float Zg = blk_sum(s2, red);
    const float invZZ = 1.f / (Zx * Zg);

    __nv_bfloat16* vo = g_V + (size_t)row * HW;
    float s = 0.f;
    for (int t = tid; t < HW; t += 256) {
        const float p = prod[t] * invZZ;                        // in (0, 1]
        const float vv = p * (1.f + p * (0.5f + p * (0.16666667f
                         + p * (0.04166667f + p * 0.00833333f))));  // expm1
        s += vv;
        vo[t] = __float2bfloat16(vv);
    }
    const float Z2 = (float)HW + blk_sum(s, red);
    if (tid == 0) g_invZ2[row] = 1.f / Z2;
}

// ---------------------------------------------------------------------------
// fold — VERBATIM R9 (reads fp32 g_X3)
// ---------------------------------------------------------------------------
__global__ void fold_kernel() {
    const int blk = blockIdx.x;              // 0..127
    const int bat = blk >> 5;
    const int i0 = (blk & 31) * 128;
    const int c = threadIdx.x;               // 0..255
    const float* X = g_X3 + ((size_t)bat * HW + i0) * CH;
    __nv_bfloat16* P = g_X3p + ((size_t)bat * HW + i0) * CH;
    const float* iz = g_invZ2 + bat * HW + i0;
    float s = 0.f;
#pragma unroll 4
    for (int r = 0; r < 128; r++) {
        const float val = X[(size_t)r * CH + c] * iz[r];
        s += val;
        P[(size_t)r * CH + c] = __float2bfloat16(val);
    }
    g_colpart[blk * CH + c] = s;
}
__global__ void colsum_reduce() {
    const int bat = blockIdx.x, c = threadIdx.x;
    float s = 0.f;
    for (int k = 0; k < 32; k++) s += g_colpart[(bat * 32 + k) * CH + c];
    g_colsum[bat * CH + c] = s;
}

// ---------------------------------------------------------------------------
// out mma — VERBATIM R9
// ---------------------------------------------------------------------------
__global__ __launch_bounds__(256) void out_mma(const float* __restrict__ x_in,
                                               float* __restrict__ out) {
    __shared__ __align__(16) __nv_bfloat16 Vs[2][32][136];
    __shared__ __align__(16) __nv_bfloat16 Xs[2][32][136];
    __shared__ float cs_s[128];
    const int bat = blockIdx.z;
    const int j0 = blockIdx.y * 128, c0 = blockIdx.x * 128;
    const __nv_bfloat16* V = g_V + (size_t)bat * HW * HW;      // [i][j]
    const __nv_bfloat16* X = g_X3p + (size_t)bat * HW * CH;    // [i][c]
    const int tid = threadIdx.x, lane = tid & 31, wid = tid >> 5;
    const int wm = wid & 1, wn = wid >> 1;
    const int vrow = tid >> 3;          // 0..31
    const int vch = (tid & 7) * 2;

    if (tid < 128) cs_s[tid] = g_colsum[bat * CH + c0 + tid];

    float acc[4][4][4] = {};

#pragma unroll 1
    for (int s = 0; s < 128; s++) {
        if (s == 0) {
#pragma unroll
            for (int q = 0; q < 2; q++) {
                cpa16(&Vs[0][vrow][(vch + q) * 8], V + (size_t)vrow * HW + j0 + (vch + q) * 8);
                cpa16(&Xs[0][vrow][(vch + q) * 8], X + (size_t)vrow * CH + c0 + (vch + q) * 8);
            }
            CP_COMMIT;
        }
        CP_WAIT0; __syncthreads();
        if (s < 127) {
            const int i0 = (s + 1) * 32, st2 = (s + 1) & 1;
#pragma unroll
            for (int q = 0; q < 2; q++) {
                cpa16(&Vs[st2][vrow][(vch + q) * 8],
                      V + (size_t)(i0 + vrow) * HW + j0 + (vch + q) * 8);
                cpa16(&Xs[st2][vrow][(vch + q) * 8],
                      X + (size_t)(i0 + vrow) * CH + c0 + (vch + q) * 8);
            }
        }
        CP_COMMIT;
        const int st = s & 1;
#pragma unroll
        for (int kk = 0; kk < 2; kk++) {
            uint32_t a[4][4], b[4][2];
#pragma unroll
            for (int mf = 0; mf < 4; mf++) {
                const int row = kk * 16 + (lane & 7) + (lane >> 4) * 8;
                const int col = wm * 64 + mf * 16 + ((lane >> 3) & 1) * 8;
                ldsm4t(a[mf], cvta_s(&Vs[st][row][col]));
            }
#pragma unroll
            for (int np = 0; np < 2; np++) {
                const int row = kk * 16 + (lane & 7) + ((lane >> 3) & 1) * 8;
                const int col = wn * 32 + np * 16 + (lane >> 4) * 8;
                uint32_t r[4];
                ldsm4t(r, cvta_s(&Xs[st][row][col]));
                b[2 * np][0] = r[0]; b[2 * np][1] = r[1];
                b[2 * np + 1][0] = r[2]; b[2 * np + 1][1] = r[3];
            }
#pragma unroll
            for (int mf = 0; mf < 4; mf++)
#pragma unroll
                for (int nf = 0; nf < 4; nf++) mma16816(acc[mf][nf], a[mf], b[nf]);
        }
        __syncthreads();
    }
#pragma unroll
    for (int mf = 0; mf < 4; mf++) {
        const int j = j0 + wm * 64 + mf * 16 + (lane >> 2);
#pragma unroll
        for (int nf = 0; nf < 4; nf++) {
            const int cc = wn * 32 + nf * 8 + (lane & 3) * 2;
            const size_t b0 = ((size_t)bat * HW + j) * CH + c0 + cc;
            float2 xv = *(const float2*)&x_in[b0];
            float2 o;
            o.x = acc[mf][nf][0] + xv.x + cs_s[cc];
            o.y = acc[mf][nf][1] + xv.y + cs_s[cc + 1];
            *(float2*)&out[b0] = o;
            const size_t b1 = ((size_t)bat * HW + j + 8) * CH + c0 + cc;
            float2 xv2 = *(const float2*)&x_in[b1];
            float2 o2;
            o2.x = acc[mf][nf][2] + xv2.x + cs_s[cc];
            o2.y = acc[mf][nf][3] + xv2.y + cs_s[cc + 1];
            *(float2*)&out[b1] = o2;
        }
    }
}

// ---------------------------------------------------------------------------
extern "C" void kernel_launch(void* const* d_in, const int* in_sizes, int n_in,
                              void* d_out, int out_size) {
    (void)in_sizes; (void)n_in; (void)out_size;
    const float* x   = (const float*)d_in[0];
    const float* g   = (const float*)d_in[1];
    float* out = (float*)d_out;

    dim3 pg(CH / 128, (BATCH * HW) / 128, 5);   // (2, 128, 5)
    proj_mma_f32<<<pg, 256>>>(x, g,
        (const float*)d_in[2],  (const float*)d_in[3],
        (const float*)d_in[4],  (const float*)d_in[5],
        (const float*)d_in[6],  (const float*)d_in[7],
        (const float*)d_in[8],  (const float*)d_in[9],
        (const float*)d_in[10], (const float*)d_in[11]);

    dim3 sg(HW / 128, HW / 128);
    for (int b = 0; b < BATCH; b++) {
        score_mma<<<sg, 256>>>(b, 1, 0, 0);  // Sx = xw2 @ xw1^T
        score_mma<<<sg, 256>>>(b, 4, 3, 1);  // Sg = gw2 @ gw1^T
    }

    row_stats_kernel<<<BATCH * HW, 256>>>();
    fold_kernel<<<128, 256>>>();
    colsum_reduce<<<BATCH, 256>>>();

    out_mma<<<dim3(CH / 128, HW / 128, BATCH), 256>>>(x, out);
}

// round 12
// speedup vs baseline: 6.7042x; 1.0836x over previous
#include <cuda_runtime.h>
#include <cuda_bf16.h>
#include <cstdint>

#define BATCH 4
#define HW    4096
#define CH    256
#define PROJ_SZ (BATCH * HW * CH)

// ---- device scratch ----
__device__ __nv_bfloat16 g_Pb[5u * PROJ_SZ];                 // projections bf16
__device__ float         g_X3[PROJ_SZ];                      // xw3 fp32
__device__ __nv_bfloat16 g_X3p[PROJ_SZ];                     // invZ2-folded xw3 bf16
__device__ __nv_bfloat16 g_Sx[(size_t)BATCH * HW * HW];
__device__ __nv_bfloat16 g_Sg[(size_t)BATCH * HW * HW];
__device__ __nv_bfloat16 g_V[(size_t)BATCH * HW * HW];
__device__ float g_invZ2[BATCH * HW];
__device__ float g_colpart[128 * CH];
__device__ float g_colsum[BATCH * CH];

// ---- mma helpers ----
__device__ __forceinline__ uint32_t cvta_s(const void* p) {
    return (uint32_t)__cvta_generic_to_shared(p);
}
__device__ __forceinline__ void ldsm4(uint32_t* r, uint32_t a) {
    asm volatile("ldmatrix.sync.aligned.m8n8.x4.shared.b16 {%0,%1,%2,%3},[%4];"
                 : "=r"(r[0]), "=r"(r[1]), "=r"(r[2]), "=r"(r[3]) : "r"(a));
}
__device__ __forceinline__ void ldsm4t(uint32_t* r, uint32_t a) {
    asm volatile("ldmatrix.sync.aligned.m8n8.x4.trans.shared.b16 {%0,%1,%2,%3},[%4];"
                 : "=r"(r[0]), "=r"(r[1]), "=r"(r[2]), "=r"(r[3]) : "r"(a));
}
__device__ __forceinline__ void mma16816(float* c, const uint32_t* a, const uint32_t* b) {
    asm volatile("mma.sync.aligned.m16n8k16.row.col.f32.bf16.bf16.f32 "
                 "{%0,%1,%2,%3},{%4,%5,%6,%7},{%8,%9},{%0,%1,%2,%3};"
                 : "+f"(c[0]), "+f"(c[1]), "+f"(c[2]), "+f"(c[3])
                 : "r"(a[0]), "r"(a[1]), "r"(a[2]), "r"(a[3]), "r"(b[0]), "r"(b[1]));
}
__device__ __forceinline__ void cpa16(void* s, const void* g) {
    asm volatile("cp.async.cg.shared.global [%0],[%1],16;" :: "r"(cvta_s(s)), "l"(g));
}
#define CP_COMMIT asm volatile("cp.async.commit_group;")
#define CP_WAIT0  asm volatile("cp.async.wait_group 0;")
#define CP_WAIT2  asm volatile("cp.async.wait_group 2;")

__device__ __forceinline__ uint2 f4b(float4 v) {
    __nv_bfloat162 lo, hi;
    lo.x = __float2bfloat16(v.x); lo.y = __float2bfloat16(v.y);
    hi.x = __float2bfloat16(v.z); hi.y = __float2bfloat16(v.w);
    uint2 r;
    r.x = *(uint32_t*)&lo;
    r.y = *(uint32_t*)&hi;
    return r;
}

// ---------------------------------------------------------------------------
// proj mma (merged z=5) — VERBATIM R10
// ---------------------------------------------------------------------------
__global__ __launch_bounds__(256) void proj_mma_f32(
    const float* __restrict__ x_in, const float* __restrict__ g_in,
    const float* __restrict__ Wx1, const float* __restrict__ bx1,
    const float* __restrict__ Wx2, const float* __restrict__ bx2,
    const float* __restrict__ Wx3, const float* __restrict__ bx3,
    const float* __restrict__ Wg1, const float* __restrict__ bg1,
    const float* __restrict__ Wg2, const float* __restrict__ bg2)
{
    __shared__ __align__(16) __nv_bfloat16 As[2][128][40];
    __shared__ __align__(16) __nv_bfloat16 Ws[2][32][136];
    const int z = blockIdx.z;
    const float* A; const float* W; const float* bias; int wantf32;
    if (z == 0)      { A = x_in; W = Wx1; bias = bx1; wantf32 = 0; }
    else if (z == 1) { A = x_in; W = Wx2; bias = bx2; wantf32 = 0; }
    else if (z == 2) { A = x_in; W = Wx3; bias = bx3; wantf32 = 1; }
    else if (z == 3) { A = g_in; W = Wg1; bias = bg1; wantf32 = 0; }
    else             { A = g_in; W = Wg2; bias = bg2; wantf32 = 0; }

    const int tid = threadIdx.x, lane = tid & 31, wid = tid >> 5;
    const int wm = wid & 1, wn = wid >> 1;
    const int m0 = blockIdx.y * 128, n0 = blockIdx.x * 128;
    __nv_bfloat16* Dst = g_Pb + (size_t)z * PROJ_SZ;

    const int arow = tid >> 1;
    const int ak   = (tid & 1) * 16;
    const int wrow = tid >> 3;
    const int wn16 = (tid & 7) * 16;

    float4 ra0, ra1, ra2, ra3, rw0, rw1, rw2, rw3;
    {
        const float* ap = A + (size_t)(m0 + arow) * CH + ak;
        ra0 = *(const float4*)(ap + 0);  ra1 = *(const float4*)(ap + 4);
        ra2 = *(const float4*)(ap + 8);  ra3 = *(const float4*)(ap + 12);
        const float* wp = W + (size_t)wrow * CH + n0 + wn16;
        rw0 = *(const float4*)(wp + 0);  rw1 = *(const float4*)(wp + 4);
        rw2 = *(const float4*)(wp + 8);  rw3 = *(const float4*)(wp + 12);
    }
    *(uint2*)&As[0][arow][ak + 0]  = f4b(ra0);
    *(uint2*)&As[0][arow][ak + 4]  = f4b(ra1);
    *(uint2*)&As[0][arow][ak + 8]  = f4b(ra2);
    *(uint2*)&As[0][arow][ak + 12] = f4b(ra3);
    *(uint2*)&Ws[0][wrow][wn16 + 0]  = f4b(rw0);
    *(uint2*)&Ws[0][wrow][wn16 + 4]  = f4b(rw1);
    *(uint2*)&Ws[0][wrow][wn16 + 8]  = f4b(rw2);
    *(uint2*)&Ws[0][wrow][wn16 + 12] = f4b(rw3);
    __syncthreads();

    float acc[4][4][4] = {};
#pragma unroll 1
    for (int s = 0; s < 8; s++) {
        if (s < 7) {
            const int k0 = (s + 1) * 32;
            const float* ap = A + (size_t)(m0 + arow) * CH + k0 + ak;
            ra0 = *(const float4*)(ap + 0);  ra1 = *(const float4*)(ap + 4);
            ra2 = *(const float4*)(ap + 8);  ra3 = *(const float4*)(ap + 12);
            const float* wp = W + (size_t)(k0 + wrow) * CH + n0 + wn16;
            rw0 = *(const float4*)(wp + 0);  rw1 = *(const float4*)(wp + 4);
            rw2 = *(const float4*)(wp + 8);  rw3 = *(const float4*)(wp + 12);
        }
        const int st = s & 1;
#pragma unroll
        for (int kk = 0; kk < 2; kk++) {
            uint32_t a[4][4], b[4][2];
#pragma unroll
            for (int mf = 0; mf < 4; mf++) {
                const int row = wm * 64 + mf * 16 + (lane & 15);
                const int ko = kk * 16 + (lane >> 4) * 8;
                ldsm4(a[mf], cvta_s(&As[st][row][ko]));
            }
#pragma unroll
            for (int np = 0; np < 2; np++) {
                const int row = kk * 16 + (lane & 7) + ((lane >> 3) & 1) * 8;
                const int col = wn * 32 + np * 16 + (lane >> 4) * 8;
                uint32_t r[4];
                ldsm4t(r, cvta_s(&Ws[st][row][col]));
                b[2 * np][0] = r[0]; b[2 * np][1] = r[1];
                b[2 * np + 1][0] = r[2]; b[2 * np + 1][1] = r[3];
            }
#pragma unroll
            for (int mf = 0; mf < 4; mf++)
#pragma unroll
                for (int nf = 0; nf < 4; nf++) mma16816(acc[mf][nf], a[mf], b[nf]);
        }
        __syncthreads();
        if (s < 7) {
            const int st2 = (s + 1) & 1;
            *(uint2*)&As[st2][arow][ak + 0]  = f4b(ra0);
            *(uint2*)&As[st2][arow][ak + 4]  = f4b(ra1);
            *(uint2*)&As[st2][arow][ak + 8]  = f4b(ra2);
            *(uint2*)&As[st2][arow][ak + 12] = f4b(ra3);
            *(uint2*)&Ws[st2][wrow][wn16 + 0]  = f4b(rw0);
            *(uint2*)&Ws[st2][wrow][wn16 + 4]  = f4b(rw1);
            *(uint2*)&Ws[st2][wrow][wn16 + 8]  = f4b(rw2);
            *(uint2*)&Ws[st2][wrow][wn16 + 12] = f4b(rw3);
            __syncthreads();
        }
    }

    const int mm0 = m0 + wm * 64, nn0 = n0 + wn * 32;
#pragma unroll
    for (int mf = 0; mf < 4; mf++) {
        const int r0 = mm0 + mf * 16 + (lane >> 2);
#pragma unroll
        for (int nf = 0; nf < 4; nf++) {
            const int col = nn0 + nf * 8 + (lane & 3) * 2;
            const float b0 = bias[col], b1 = bias[col + 1];
            const float f0 = acc[mf][nf][0] + b0, f1 = acc[mf][nf][1] + b1;
            const float f2 = acc[mf][nf][2] + b0, f3 = acc[mf][nf][3] + b1;
            __nv_bfloat162 v0, v1;
            v0.x = __float2bfloat16(f0); v0.y = __float2bfloat16(f1);
            v1.x = __float2bfloat16(f2); v1.y = __float2bfloat16(f3);
            *(__nv_bfloat162*)&Dst[(size_t)r0 * CH + col] = v0;
            *(__nv_bfloat162*)&Dst[(size_t)(r0 + 8) * CH + col] = v1;
            if (wantf32) {
                float2 w0; w0.x = f0; w0.y = f1;
                float2 w1; w1.x = f2; w1.y = f3;
                *(float2*)&g_X3[(size_t)r0 * CH + col] = w0;
                *(float2*)&g_X3[(size_t)(r0 + 8) * CH + col] = w1;
            }
        }
    }
}

// ---------------------------------------------------------------------------
// score_ms: 4-stage cp.async pipelined mma.sync score GEMM, merged launch.
// grid (32, 32, 8): z -> bat = z>>1, branch = z&1.
// Dst[128,128] = A[128,256] @ B[128,256]^T ; dynamic smem 81920 B.
// ---------------------------------------------------------------------------
#define SC_TILE 5120   // 128 rows * 40 elems per stage

__global__ __launch_bounds__(256) void score_ms() {
    extern __shared__ __align__(16) __nv_bfloat16 sm[];
    __nv_bfloat16* Asm = sm;                       // 4 stages
    __nv_bfloat16* Bsm = sm + 4 * SC_TILE;         // 4 stages
    const int tid = threadIdx.x, lane = tid & 31, wid = tid >> 5;
    const int wm = wid & 1, wn = wid >> 1;
    const int lrow = tid >> 1, lch = (tid & 1) * 2;
    const int z = blockIdx.z, bat = z >> 1, branch = z & 1;
    const __nv_bfloat16* A  = g_Pb + (size_t)(branch ? 4 : 1) * PROJ_SZ
                              + (size_t)bat * HW * CH + (size_t)blockIdx.y * 128 * CH;
    const __nv_bfloat16* Bm = g_Pb + (size_t)(branch ? 3 : 0) * PROJ_SZ
                              + (size_t)bat * HW * CH + (size_t)blockIdx.x * 128 * CH;
    __nv_bfloat16* Dst = (branch ? g_Sg : g_Sx) + (size_t)bat * HW * HW;

    // prefetch stages 0..2
#pragma unroll
    for (int s = 0; s < 3; s++) {
        const int k0 = s * 32;
        __nv_bfloat16* Ad = Asm + s * SC_TILE;
        __nv_bfloat16* Bd = Bsm + s * SC_TILE;
#pragma unroll
        for (int q = 0; q < 2; q++) {
            cpa16(&Ad[lrow * 40 + (lch + q) * 8], A + (size_t)lrow * CH + k0 + (lch + q) * 8);
            cpa16(&Bd[lrow * 40 + (lch + q) * 8], Bm + (size_t)lrow * CH + k0 + (lch + q) * 8);
        }
        CP_COMMIT;
    }

    float acc[4][4][4] = {};
#pragma unroll 1
    for (int s = 0; s < 8; s++) {
        CP_WAIT2;            // oldest outstanding group (stage s) complete
        __syncthreads();
        const int st = s & 3;
        const __nv_bfloat16* Ap = Asm + st * SC_TILE;
        const __nv_bfloat16* Bp = Bsm + st * SC_TILE;
#pragma unroll
        for (int kk = 0; kk < 2; kk++) {
            uint32_t a[4][4], b[4][2];
#pragma unroll
            for (int mf = 0; mf < 4; mf++) {
                const int row = wm * 64 + mf * 16 + (lane & 15);
                const int ko = kk * 16 + (lane >> 4) * 8;
                ldsm4(a[mf], cvta_s(&Ap[row * 40 + ko]));
            }
#pragma unroll
            for (int np = 0; np < 2; np++) {
                const int row = wn * 32 + np * 16 + (lane & 7) + (lane >> 4) * 8;
                const int ko = kk * 16 + ((lane >> 3) & 1) * 8;
                uint32_t r[4];
                ldsm4(r, cvta_s(&Bp[row * 40 + ko]));
                b[2 * np][0] = r[0]; b[2 * np][1] = r[1];
                b[2 * np + 1][0] = r[2]; b[2 * np + 1][1] = r[3];
            }
#pragma unroll
            for (int mf = 0; mf < 4; mf++)
#pragma unroll
                for (int nf = 0; nf < 4; nf++) mma16816(acc[mf][nf], a[mf], b[nf]);
        }
        if (s < 5) {
            const int k0 = (s + 3) * 32, st2 = (s + 3) & 3;
            __nv_bfloat16* Ad = Asm + st2 * SC_TILE;
            __nv_bfloat16* Bd = Bsm + st2 * SC_TILE;
#pragma unroll
            for (int q = 0; q < 2; q++) {
                cpa16(&Ad[lrow * 40 + (lch + q) * 8],
                      A + (size_t)lrow * CH + k0 + (lch + q) * 8);
                cpa16(&Bd[lrow * 40 + (lch + q) * 8],
                      Bm + (size_t)lrow * CH + k0 + (lch + q) * 8);
            }
        }
        CP_COMMIT;           // empty group when s>=5 keeps group counts aligned
    }

    const int m0 = blockIdx.y * 128 + wm * 64, n0 = blockIdx.x * 128 + wn * 32;
#pragma unroll
    for (int mf = 0; mf < 4; mf++) {
        const int r0 = m0 + mf * 16 + (lane >> 2);
#pragma unroll
        for (int nf = 0; nf < 4; nf++) {
            const int col = n0 + nf * 8 + (lane & 3) * 2;
            __nv_bfloat162 v0, v1;
            v0.x = __float2bfloat16(acc[mf][nf][0]); v0.y = __float2bfloat16(acc[mf][nf][1]);
            v1.x = __float2bfloat16(acc[mf][nf][2]); v1.y = __float2bfloat16(acc[mf][nf][3]);
            *(__nv_bfloat162*)&Dst[(size_t)r0 * HW + col] = v0;
            *(__nv_bfloat162*)&Dst[(size_t)(r0 + 8) * HW + col] = v1;
        }
    }
}
#define SC_SMEM_BYTES (8 * SC_TILE * 2)   // 81920

// ---------------------------------------------------------------------------
// score mma — VERBATIM R10 (fallback if smem attribute fails)
// ---------------------------------------------------------------------------
__global__ __launch_bounds__(256) void score_mma(int bat, int aw, int bw, int dest) {
    __shared__ __align__(16) __nv_bfloat16 As[2][128][40];
    __shared__ __align__(16) __nv_bfloat16 Bs[2][128][40];
    const __nv_bfloat16* A  = g_Pb + (size_t)aw * PROJ_SZ + (size_t)bat * HW * CH
                              + (size_t)blockIdx.y * 128 * CH;
    const __nv_bfloat16* Bm = g_Pb + (size_t)bw * PROJ_SZ + (size_t)bat * HW * CH
                              + (size_t)blockIdx.x * 128 * CH;
    __nv_bfloat16* Dst = (dest ? g_Sg : g_Sx) + (size_t)bat * HW * HW;
    const int tid = threadIdx.x, lane = tid & 31, wid = tid >> 5;
    const int wm = wid & 1, wn = wid >> 1;
    const int lrow = tid >> 1, lch = (tid & 1) * 2;

    float acc[4][4][4] = {};
#pragma unroll 1
    for (int s = 0; s < 8; s++) {
        if (s == 0) {
#pragma unroll
            for (int q = 0; q < 2; q++) {
                cpa16(&As[0][lrow][(lch + q) * 8], A + (size_t)lrow * CH + (lch + q) * 8);
                cpa16(&Bs[0][lrow][(lch + q) * 8], Bm + (size_t)lrow * CH + (lch + q) * 8);
            }
            CP_COMMIT;
        }
        CP_WAIT0; __syncthreads();
        if (s < 7) {
            const int k0 = (s + 1) * 32, st2 = (s + 1) & 1;
#pragma unroll
            for (int q = 0; q < 2; q++) {
                cpa16(&As[st2][lrow][(lch + q) * 8], A + (size_t)lrow * CH + k0 + (lch + q) * 8);
                cpa16(&Bs[st2][lrow][(lch + q) * 8], Bm + (size_t)lrow * CH + k0 + (lch + q) * 8);
            }
        }
        CP_COMMIT;
        const int st = s & 1;
#pragma unroll
        for (int kk = 0; kk < 2; kk++) {
            uint32_t a[4][4], b[4][2];
#pragma unroll
            for (int mf = 0; mf < 4; mf++) {
                const int row = wm * 64 + mf * 16 + (lane & 15);
                const int ko = kk * 16 + (lane >> 4) * 8;
                ldsm4(a[mf], cvta_s(&As[st][row][ko]));
            }
#pragma unroll
            for (int np = 0; np < 2; np++) {
                const int row = wn * 32 + np * 16 + (lane & 7) + (lane >> 4) * 8;
                const int ko = kk * 16 + ((lane >> 3) & 1) * 8;
                uint32_t r[4];
                ldsm4(r, cvta_s(&Bs[st][row][ko]));
                b[2 * np][0] = r[0]; b[2 * np][1] = r[1];
                b[2 * np + 1][0] = r[2]; b[2 * np + 1][1] = r[3];
            }
#pragma unroll
            for (int mf = 0; mf < 4; mf++)
#pragma unroll
                for (int nf = 0; nf < 4; nf++) mma16816(acc[mf][nf], a[mf], b[nf]);
        }
        __syncthreads();
    }
    const int m0 = blockIdx.y * 128 + wm * 64, n0 = blockIdx.x * 128 + wn * 32;
#pragma unroll
    for (int mf = 0; mf < 4; mf++) {
        const int r0 = m0 + mf * 16 + (lane >> 2);
#pragma unroll
        for (int nf = 0; nf < 4; nf++) {
            const int col = n0 + nf * 8 + (lane & 3) * 2;
            __nv_bfloat162 v0, v1;
            v0.x = __float2bfloat16(acc[mf][nf][0]); v0.y = __float2bfloat16(acc[mf][nf][1]);
            v1.x = __float2bfloat16(acc[mf][nf][2]); v1.y = __float2bfloat16(acc[mf][nf][3]);
            *(__nv_bfloat162*)&Dst[(size_t)r0 * HW + col] = v0;
            *(__nv_bfloat162*)&Dst[(size_t)(r0 + 8) * HW + col] = v1;
        }
    }
}

// ---------------------------------------------------------------------------
// row stats — VERBATIM R10
// ---------------------------------------------------------------------------
__device__ __forceinline__ float blk_sum(float v, float* red) {
    int tid = threadIdx.x;
    red[tid] = v; __syncthreads();
    for (int s = 128; s > 0; s >>= 1) {
        if (tid < s) red[tid] += red[tid + s];
        __syncthreads();
    }
    float r = red[0]; __syncthreads();
    return r;
}

__global__ void row_stats_kernel() {
    __shared__ float prod[HW];
    __shared__ float red[256];
    const int row = blockIdx.x;
    const int tid = threadIdx.x;
    const __nv_bfloat16* px = g_Sx + (size_t)row * HW;
    const __nv_bfloat16* pg = g_Sg + (size_t)row * HW;

    float s1 = 0.f, s2 = 0.f;
    for (int t = tid; t < HW / 4; t += 256) {
        __nv_bfloat162 x0 = *(const __nv_bfloat162*)&px[t * 4];
        __nv_bfloat162 x1 = *(const __nv_bfloat162*)&px[t * 4 + 2];
        __nv_bfloat162 g0 = *(const __nv_bfloat162*)&pg[t * 4];
        __nv_bfloat162 g1 = *(const __nv_bfloat162*)&pg[t * 4 + 2];
        const float ex0 = __expf(__bfloat162float(x0.x));
        const float ex1 = __expf(__bfloat162float(x0.y));
        const float ex2 = __expf(__bfloat162float(x1.x));
        const float ex3 = __expf(__bfloat162float(x1.y));
        const float eg0 = __expf(__bfloat162float(g0.x));
        const float eg1 = __expf(__bfloat162float(g0.y));
        const float eg2 = __expf(__bfloat162float(g1.x));
        const float eg3 = __expf(__bfloat162float(g1.y));
        s1 += ex0 + ex1 + ex2 + ex3;
        s2 += eg0 + eg1 + eg2 + eg3;
        prod[t * 4 + 0] = ex0 * eg0;
        prod[t * 4 + 1] = ex1 * eg1;
        prod[t * 4 + 2] = ex2 * eg2;
        prod[t * 4 + 3] = ex3 * eg3;
    }
    __syncthreads();
    const float Zx = blk_sum(s1, red);
    const float Zg = blk_sum(s2, red);
    const float invZZ = 1.f / (Zx * Zg);

    __nv_bfloat16* vo = g_V + (size_t)row * HW;
    float s = 0.f;
    for (int t = tid; t < HW; t += 256) {
        const float p = prod[t] * invZZ;
        const float vv = p * (1.f + p * (0.5f + p * (0.16666667f
                         + p * (0.04166667f + p * 0.00833333f))));
        s += vv;
        vo[t] = __float2bfloat16(vv);
    }
    const float Z2 = (float)HW + blk_sum(s, red);
    if (tid == 0) g_invZ2[row] = 1.f / Z2;
}

// ---------------------------------------------------------------------------
// fold + colsum — VERBATIM R10
// ---------------------------------------------------------------------------
__global__ void fold_kernel() {
    const int blk = blockIdx.x;
    const int bat = blk >> 5;
    const int i0 = (blk & 31) * 128;
    const int c = threadIdx.x;
    const float* X = g_X3 + ((size_t)bat * HW + i0) * CH;
    __nv_bfloat16* P = g_X3p + ((size_t)bat * HW + i0) * CH;
    const float* iz = g_invZ2 + bat * HW + i0;
    float s = 0.f;
#pragma unroll 4
    for (int r = 0; r < 128; r++) {
        const float val = X[(size_t)r * CH + c] * iz[r];
        s += val;
        P[(size_t)r * CH + c] = __float2bfloat16(val);
    }
    g_colpart[blk * CH + c] = s;
}
__global__ void colsum_reduce() {
    const int bat = blockIdx.x, c = threadIdx.x;
    float s = 0.f;
    for (int k = 0; k < 32; k++) s += g_colpart[(bat * 32 + k) * CH + c];
    g_colsum[bat * CH + c] = s;
}

// ---------------------------------------------------------------------------
// out mma — VERBATIM R10
// ---------------------------------------------------------------------------
__global__ __launch_bounds__(256) void out_mma(const float* __restrict__ x_in,
                                               float* __restrict__ out) {
    __shared__ __align__(16) __nv_bfloat16 Vs[2][32][136];
    __shared__ __align__(16) __nv_bfloat16 Xs[2][32][136];
    __shared__ float cs_s[128];
    const int bat = blockIdx.z;
    const int j0 = blockIdx.y * 128, c0 = blockIdx.x * 128;
    const __nv_bfloat16* V = g_V + (size_t)bat * HW * HW;
    const __nv_bfloat16* X = g_X3p + (size_t)bat * HW * CH;
    const int tid = threadIdx.x, lane = tid & 31, wid = tid >> 5;
    const int wm = wid & 1, wn = wid >> 1;
    const int vrow = tid >> 3;
    const int vch = (tid & 7) * 2;

    if (tid < 128) cs_s[tid] = g_colsum[bat * CH + c0 + tid];

    float acc[4][4][4] = {};

#pragma unroll 1
    for (int s = 0; s < 128; s++) {
        if (s == 0) {
#pragma unroll
            for (int q = 0; q < 2; q++) {
                cpa16(&Vs[0][vrow][(vch + q) * 8], V + (size_t)vrow * HW + j0 + (vch + q) * 8);
                cpa16(&Xs[0][vrow][(vch + q) * 8], X + (size_t)vrow * CH + c0 + (vch + q) * 8);
            }
            CP_COMMIT;
        }
        CP_WAIT0; __syncthreads();
        if (s < 127) {
            const int i0 = (s + 1) * 32, st2 = (s + 1) & 1;
#pragma unroll
            for (int q = 0; q < 2; q++) {
                cpa16(&Vs[st2][vrow][(vch + q) * 8],
                      V + (size_t)(i0 + vrow) * HW + j0 + (vch + q) * 8);
                cpa16(&Xs[st2][vrow][(vch + q) * 8],
                      X + (size_t)(i0 + vrow) * CH + c0 + (vch + q) * 8);
            }
        }
        CP_COMMIT;
        const int st = s & 1;
#pragma unroll
        for (int kk = 0; kk < 2; kk++) {
            uint32_t a[4][4], b[4][2];
#pragma unroll
            for (int mf = 0; mf < 4; mf++) {
                const int row = kk * 16 + (lane & 7) + (lane >> 4) * 8;
                const int col = wm * 64 + mf * 16 + ((lane >> 3) & 1) * 8;
                ldsm4t(a[mf], cvta_s(&Vs[st][row][col]));
            }
#pragma unroll
            for (int np = 0; np < 2; np++) {
                const int row = kk * 16 + (lane & 7) + ((lane >> 3) & 1) * 8;
                const int col = wn * 32 + np * 16 + (lane >> 4) * 8;
                uint32_t r[4];
                ldsm4t(r, cvta_s(&Xs[st][row][col]));
                b[2 * np][0] = r[0]; b[2 * np][1] = r[1];
                b[2 * np + 1][0] = r[2]; b[2 * np + 1][1] = r[3];
            }
#pragma unroll
            for (int mf = 0; mf < 4; mf++)
#pragma unroll
                for (int nf = 0; nf < 4; nf++) mma16816(acc[mf][nf], a[mf], b[nf]);
        }
        __syncthreads();
    }
#pragma unroll
    for (int mf = 0; mf < 4; mf++) {
        const int j = j0 + wm * 64 + mf * 16 + (lane >> 2);
#pragma unroll
        for (int nf = 0; nf < 4; nf++) {
            const int cc = wn * 32 + nf * 8 + (lane & 3) * 2;
            const size_t b0 = ((size_t)bat * HW + j) * CH + c0 + cc;
            float2 xv = *(const float2*)&x_in[b0];
            float2 o;
            o.x = acc[mf][nf][0] + xv.x + cs_s[cc];
            o.y = acc[mf][nf][1] + xv.y + cs_s[cc + 1];
            *(float2*)&out[b0] = o;
            const size_t b1 = ((size_t)bat * HW + j + 8) * CH + cc + c0;
            float2 xv2 = *(const float2*)&x_in[b1];
            float2 o2;
            o2.x = acc[mf][nf][2] + xv2.x + cs_s[cc];
            o2.y = acc[mf][nf][3] + xv2.y + cs_s[cc + 1];
            *(float2*)&out[b1] = o2;
        }
    }
}

// ---------------------------------------------------------------------------
extern "C" void kernel_launch(void* const* d_in, const int* in_sizes, int n_in,
                              void* d_out, int out_size) {
    (void)in_sizes; (void)n_in; (void)out_size;
    const float* x   = (const float*)d_in[0];
    const float* g   = (const float*)d_in[1];
    float* out = (float*)d_out;

    dim3 pg(CH / 128, (BATCH * HW) / 128, 5);
    proj_mma_f32<<<pg, 256>>>(x, g,
        (const float*)d_in[2],  (const float*)d_in[3],
        (const float*)d_in[4],  (const float*)d_in[5],
        (const float*)d_in[6],  (const float*)d_in[7],
        (const float*)d_in[8],  (const float*)d_in[9],
        (const float*)d_in[10], (const float*)d_in[11]);

    if (cudaFuncSetAttribute(score_ms, cudaFuncAttributeMaxDynamicSharedMemorySize,
                             SC_SMEM_BYTES) == cudaSuccess) {
        score_ms<<<dim3(32, 32, 8), 256, SC_SMEM_BYTES>>>();
    } else {
        dim3 sg(HW / 128, HW / 128);
        for (int b = 0; b < BATCH; b++) {
            score_mma<<<sg, 256>>>(b, 1, 0, 0);
            score_mma<<<sg, 256>>>(b, 4, 3, 1);
        }
    }

    row_stats_kernel<<<BATCH * HW, 256>>>();
    fold_kernel<<<128, 256>>>();
    colsum_reduce<<<BATCH, 256>>>();

    out_mma<<<dim3(CH / 128, HW / 128, BATCH), 256>>>(x, out);
}

// round 14
// speedup vs baseline: 7.4129x; 1.1057x over previous
#include <cuda_runtime.h>
#include <cuda_bf16.h>
#include <cstdint>

#define BATCH 4
#define HW    4096
#define CH    256
#define PROJ_SZ (BATCH * HW * CH)

// ---- device scratch ----
__device__ __nv_bfloat16 g_Pb[5u * PROJ_SZ];                 // projections bf16
__device__ float         g_X3[PROJ_SZ];                      // xw3 fp32
__device__ __nv_bfloat16 g_X3p[PROJ_SZ];                     // invZ2-folded xw3 bf16
__device__ __nv_bfloat16 g_Sx[(size_t)BATCH * HW * HW];
__device__ __nv_bfloat16 g_Sg[(size_t)BATCH * HW * HW];
__device__ __nv_bfloat16 g_V[(size_t)BATCH * HW * HW];
__device__ float g_invZ2[BATCH * HW];
__device__ float g_colpart[2048 * CH];
__device__ float g_colpart2[128 * CH];
__device__ float g_colsum[BATCH * CH];

// ---- mma helpers ----
__device__ __forceinline__ uint32_t cvta_s(const void* p) {
    return (uint32_t)__cvta_generic_to_shared(p);
}
__device__ __forceinline__ void ldsm4(uint32_t* r, uint32_t a) {
    asm volatile("ldmatrix.sync.aligned.m8n8.x4.shared.b16 {%0,%1,%2,%3},[%4];"
                 : "=r"(r[0]), "=r"(r[1]), "=r"(r[2]), "=r"(r[3]) : "r"(a));
}
__device__ __forceinline__ void ldsm4t(uint32_t* r, uint32_t a) {
    asm volatile("ldmatrix.sync.aligned.m8n8.x4.trans.shared.b16 {%0,%1,%2,%3},[%4];"
                 : "=r"(r[0]), "=r"(r[1]), "=r"(r[2]), "=r"(r[3]) : "r"(a));
}
__device__ __forceinline__ void mma16816(float* c, const uint32_t* a, const uint32_t* b) {
    asm volatile("mma.sync.aligned.m16n8k16.row.col.f32.bf16.bf16.f32 "
                 "{%0,%1,%2,%3},{%4,%5,%6,%7},{%8,%9},{%0,%1,%2,%3};"
                 : "+f"(c[0]), "+f"(c[1]), "+f"(c[2]), "+f"(c[3])
                 : "r"(a[0]), "r"(a[1]), "r"(a[2]), "r"(a[3]), "r"(b[0]), "r"(b[1]));
}
__device__ __forceinline__ void cpa16(void* s, const void* g) {
    asm volatile("cp.async.cg.shared.global [%0],[%1],16;" :: "r"(cvta_s(s)), "l"(g));
}
#define CP_COMMIT asm volatile("cp.async.commit_group;")
#define CP_WAIT0  asm volatile("cp.async.wait_group 0;")
#define CP_WAIT2  asm volatile("cp.async.wait_group 2;")

__device__ __forceinline__ uint2 f4b(float4 v) {
    __nv_bfloat162 lo, hi;
    lo.x = __float2bfloat16(v.x); lo.y = __float2bfloat16(v.y);
    hi.x = __float2bfloat16(v.z); hi.y = __float2bfloat16(v.w);
    uint2 r;
    r.x = *(uint32_t*)&lo;
    r.y = *(uint32_t*)&hi;
    return r;
}

// ---------------------------------------------------------------------------
// proj mma (merged z=5) — VERBATIM R12
// ---------------------------------------------------------------------------
__global__ __launch_bounds__(256) void proj_mma_f32(
    const float* __restrict__ x_in, const float* __restrict__ g_in,
    const float* __restrict__ Wx1, const float* __restrict__ bx1,
    const float* __restrict__ Wx2, const float* __restrict__ bx2,
    const float* __restrict__ Wx3, const float* __restrict__ bx3,
    const float* __restrict__ Wg1, const float* __restrict__ bg1,
    const float* __restrict__ Wg2, const float* __restrict__ bg2)
{
    __shared__ __align__(16) __nv_bfloat16 As[2][128][40];
    __shared__ __align__(16) __nv_bfloat16 Ws[2][32][136];
    const int z = blockIdx.z;
    const float* A; const float* W; const float* bias; int wantf32;
    if (z == 0)      { A = x_in; W = Wx1; bias = bx1; wantf32 = 0; }
    else if (z == 1) { A = x_in; W = Wx2; bias = bx2; wantf32 = 0; }
    else if (z == 2) { A = x_in; W = Wx3; bias = bx3; wantf32 = 1; }
    else if (z == 3) { A = g_in; W = Wg1; bias = bg1; wantf32 = 0; }
    else             { A = g_in; W = Wg2; bias = bg2; wantf32 = 0; }

    const int tid = threadIdx.x, lane = tid & 31, wid = tid >> 5;
    const int wm = wid & 1, wn = wid >> 1;
    const int m0 = blockIdx.y * 128, n0 = blockIdx.x * 128;
    __nv_bfloat16* Dst = g_Pb + (size_t)z * PROJ_SZ;

    const int arow = tid >> 1;
    const int ak   = (tid & 1) * 16;
    const int wrow = tid >> 3;
    const int wn16 = (tid & 7) * 16;

    float4 ra0, ra1, ra2, ra3, rw0, rw1, rw2, rw3;
    {
        const float* ap = A + (size_t)(m0 + arow) * CH + ak;
        ra0 = *(const float4*)(ap + 0);  ra1 = *(const float4*)(ap + 4);
        ra2 = *(const float4*)(ap + 8);  ra3 = *(const float4*)(ap + 12);
        const float* wp = W + (size_t)wrow * CH + n0 + wn16;
        rw0 = *(const float4*)(wp + 0);  rw1 = *(const float4*)(wp + 4);
        rw2 = *(const float4*)(wp + 8);  rw3 = *(const float4*)(wp + 12);
    }
    *(uint2*)&As[0][arow][ak + 0]  = f4b(ra0);
    *(uint2*)&As[0][arow][ak + 4]  = f4b(ra1);
    *(uint2*)&As[0][arow][ak + 8]  = f4b(ra2);
    *(uint2*)&As[0][arow][ak + 12] = f4b(ra3);
    *(uint2*)&Ws[0][wrow][wn16 + 0]  = f4b(rw0);
    *(uint2*)&Ws[0][wrow][wn16 + 4]  = f4b(rw1);
    *(uint2*)&Ws[0][wrow][wn16 + 8]  = f4b(rw2);
    *(uint2*)&Ws[0][wrow][wn16 + 12] = f4b(rw3);
    __syncthreads();

    float acc[4][4][4] = {};
#pragma unroll 1
    for (int s = 0; s < 8; s++) {
        if (s < 7) {
            const int k0 = (s + 1) * 32;
            const float* ap = A + (size_t)(m0 + arow) * CH + k0 + ak;
            ra0 = *(const float4*)(ap + 0);  ra1 = *(const float4*)(ap + 4);
            ra2 = *(const float4*)(ap + 8);  ra3 = *(const float4*)(ap + 12);
            const float* wp = W + (size_t)(k0 + wrow) * CH + n0 + wn16;
            rw0 = *(const float4*)(wp + 0);  rw1 = *(const float4*)(wp + 4);
            rw2 = *(const float4*)(wp + 8);  rw3 = *(const float4*)(wp + 12);
        }
        const int st = s & 1;
#pragma unroll
        for (int kk = 0; kk < 2; kk++) {
            uint32_t a[4][4], b[4][2];
#pragma unroll
            for (int mf = 0; mf < 4; mf++) {
                const int row = wm * 64 + mf * 16 + (lane & 15);
                const int ko = kk * 16 + (lane >> 4) * 8;
                ldsm4(a[mf], cvta_s(&As[st][row][ko]));
            }
#pragma unroll
            for (int np = 0; np < 2; np++) {
                const int row = kk * 16 + (lane & 7) + ((lane >> 3) & 1) * 8;
                const int col = wn * 32 + np * 16 + (lane >> 4) * 8;
                uint32_t r[4];
                ldsm4t(r, cvta_s(&Ws[st][row][col]));
                b[2 * np][0] = r[0]; b[2 * np][1] = r[1];
                b[2 * np + 1][0] = r[2]; b[2 * np + 1][1] = r[3];
            }
#pragma unroll
            for (int mf = 0; mf < 4; mf++)
#pragma unroll
                for (int nf = 0; nf < 4; nf++) mma16816(acc[mf][nf], a[mf], b[nf]);
        }
        __syncthreads();
        if (s < 7) {
            const int st2 = (s + 1) & 1;
            *(uint2*)&As[st2][arow][ak + 0]  = f4b(ra0);
            *(uint2*)&As[st2][arow][ak + 4]  = f4b(ra1);
            *(uint2*)&As[st2][arow][ak + 8]  = f4b(ra2);
            *(uint2*)&As[st2][arow][ak + 12] = f4b(ra3);
            *(uint2*)&Ws[st2][wrow][wn16 + 0]  = f4b(rw0);
            *(uint2*)&Ws[st2][wrow][wn16 + 4]  = f4b(rw1);
            *(uint2*)&Ws[st2][wrow][wn16 + 8]  = f4b(rw2);
            *(uint2*)&Ws[st2][wrow][wn16 + 12] = f4b(rw3);
            __syncthreads();
        }
    }

    const int mm0 = m0 + wm * 64, nn0 = n0 + wn * 32;
#pragma unroll
    for (int mf = 0; mf < 4; mf++) {
        const int r0 = mm0 + mf * 16 + (lane >> 2);
#pragma unroll
        for (int nf = 0; nf < 4; nf++) {
            const int col = nn0 + nf * 8 + (lane & 3) * 2;
            const float b0 = bias[col], b1 = bias[col + 1];
            const float f0 = acc[mf][nf][0] + b0, f1 = acc[mf][nf][1] + b1;
            const float f2 = acc[mf][nf][2] + b0, f3 = acc[mf][nf][3] + b1;
            __nv_bfloat162 v0, v1;
            v0.x = __float2bfloat16(f0); v0.y = __float2bfloat16(f1);
            v1.x = __float2bfloat16(f2); v1.y = __float2bfloat16(f3);
            *(__nv_bfloat162*)&Dst[(size_t)r0 * CH + col] = v0;
            *(__nv_bfloat162*)&Dst[(size_t)(r0 + 8) * CH + col] = v1;
            if (wantf32) {
                float2 w0; w0.x = f0; w0.y = f1;
                float2 w1; w1.x = f2; w1.y = f3;
                *(float2*)&g_X3[(size_t)r0 * CH + col] = w0;
                *(float2*)&g_X3[(size_t)(r0 + 8) * CH + col] = w1;
            }
        }
    }
}

// ---------------------------------------------------------------------------
// score_ms — VERBATIM R12 (4-stage cp.async pipeline, merged launch)
// ---------------------------------------------------------------------------
#define SC_TILE 5120   // 128 rows * 40 elems per stage

__global__ __launch_bounds__(256) void score_ms() {
    extern __shared__ __align__(16) __nv_bfloat16 sm[];
    __nv_bfloat16* Asm = sm;
    __nv_bfloat16* Bsm = sm + 4 * SC_TILE;
    const int tid = threadIdx.x, lane = tid & 31, wid = tid >> 5;
    const int wm = wid & 1, wn = wid >> 1;
    const int lrow = tid >> 1, lch = (tid & 1) * 2;
    const int z = blockIdx.z, bat = z >> 1, branch = z & 1;
    const __nv_bfloat16* A  = g_Pb + (size_t)(branch ? 4 : 1) * PROJ_SZ
                              + (size_t)bat * HW * CH + (size_t)blockIdx.y * 128 * CH;
    const __nv_bfloat16* Bm = g_Pb + (size_t)(branch ? 3 : 0) * PROJ_SZ
                              + (size_t)bat * HW * CH + (size_t)blockIdx.x * 128 * CH;
    __nv_bfloat16* Dst = (branch ? g_Sg : g_Sx) + (size_t)bat * HW * HW;

#pragma unroll
    for (int s = 0; s < 3; s++) {
        const int k0 = s * 32;
        __nv_bfloat16* Ad = Asm + s * SC_TILE;
        __nv_bfloat16* Bd = Bsm + s * SC_TILE;
#pragma unroll
        for (int q = 0; q < 2; q++) {
            cpa16(&Ad[lrow * 40 + (lch + q) * 8], A + (size_t)lrow * CH + k0 + (lch + q) * 8);
            cpa16(&Bd[lrow * 40 + (lch + q) * 8], Bm + (size_t)lrow * CH + k0 + (lch + q) * 8);
        }
        CP_COMMIT;
    }

    float acc[4][4][4] = {};
#pragma unroll 1
    for (int s = 0; s < 8; s++) {
        CP_WAIT2;
        __syncthreads();
        const int st = s & 3;
        const __nv_bfloat16* Ap = Asm + st * SC_TILE;
        const __nv_bfloat16* Bp = Bsm + st * SC_TILE;
#pragma unroll
        for (int kk = 0; kk < 2; kk++) {
            uint32_t a[4][4], b[4][2];
#pragma unroll
            for (int mf = 0; mf < 4; mf++) {
                const int row = wm * 64 + mf * 16 + (lane & 15);
                const int ko = kk * 16 + (lane >> 4) * 8;
                ldsm4(a[mf], cvta_s(&Ap[row * 40 + ko]));
            }
#pragma unroll
            for (int np = 0; np < 2; np++) {
                const int row = wn * 32 + np * 16 + (lane & 7) + (lane >> 4) * 8;
                const int ko = kk * 16 + ((lane >> 3) & 1) * 8;
                uint32_t r[4];
                ldsm4(r, cvta_s(&Bp[row * 40 + ko]));
                b[2 * np][0] = r[0]; b[2 * np][1] = r[1];
                b[2 * np + 1][0] = r[2]; b[2 * np + 1][1] = r[3];
            }
#pragma unroll
            for (int mf = 0; mf < 4; mf++)
#pragma unroll
                for (int nf = 0; nf < 4; nf++) mma16816(acc[mf][nf], a[mf], b[nf]);
        }
        if (s < 5) {
            const int k0 = (s + 3) * 32, st2 = (s + 3) & 3;
            __nv_bfloat16* Ad = Asm + st2 * SC_TILE;
            __nv_bfloat16* Bd = Bsm + st2 * SC_TILE;
#pragma unroll
            for (int q = 0; q < 2; q++) {
                cpa16(&Ad[lrow * 40 + (lch + q) * 8],
                      A + (size_t)lrow * CH + k0 + (lch + q) * 8);
                cpa16(&Bd[lrow * 40 + (lch + q) * 8],
                      Bm + (size_t)lrow * CH + k0 + (lch + q) * 8);
            }
        }
        CP_COMMIT;
    }

    const int m0 = blockIdx.y * 128 + wm * 64, n0 = blockIdx.x * 128 + wn * 32;
#pragma unroll
    for (int mf = 0; mf < 4; mf++) {
        const int r0 = m0 + mf * 16 + (lane >> 2);
#pragma unroll
        for (int nf = 0; nf < 4; nf++) {
            const int col = n0 + nf * 8 + (lane & 3) * 2;
            __nv_bfloat162 v0, v1;
            v0.x = __float2bfloat16(acc[mf][nf][0]); v0.y = __float2bfloat16(acc[mf][nf][1]);
            v1.x = __float2bfloat16(acc[mf][nf][2]); v1.y = __float2bfloat16(acc[mf][nf][3]);
            *(__nv_bfloat162*)&Dst[(size_t)r0 * HW + col] = v0;
            *(__nv_bfloat162*)&Dst[(size_t)(r0 + 8) * HW + col] = v1;
        }
    }
}
#define SC_SMEM_BYTES (8 * SC_TILE * 2)   // 81920

// ---------------------------------------------------------------------------
// row stats — VERBATIM R12
// ---------------------------------------------------------------------------
__device__ __forceinline__ float blk_sum(float v, float* red) {
    int tid = threadIdx.x;
    red[tid] = v; __syncthreads();
    for (int s = 128; s > 0; s >>= 1) {
        if (tid < s) red[tid] += red[tid + s];
        __syncthreads();
    }
    float r = red[0]; __syncthreads();
    return r;
}

__global__ void row_stats_kernel() {
    __shared__ float prod[HW];
    __shared__ float red[256];
    const int row = blockIdx.x;
    const int tid = threadIdx.x;
    const __nv_bfloat16* px = g_Sx + (size_t)row * HW;
    const __nv_bfloat16* pg = g_Sg + (size_t)row * HW;

    float s1 = 0.f, s2 = 0.f;
    for (int t = tid; t < HW / 4; t += 256) {
        __nv_bfloat162 x0 = *(const __nv_bfloat162*)&px[t * 4];
        __nv_bfloat162 x1 = *(const __nv_bfloat162*)&px[t * 4 + 2];
        __nv_bfloat162 g0 = *(const __nv_bfloat162*)&pg[t * 4];
        __nv_bfloat162 g1 = *(const __nv_bfloat162*)&pg[t * 4 + 2];
        const float ex0 = __expf(__bfloat162float(x0.x));
        const float ex1 = __expf(__bfloat162float(x0.y));
        const float ex2 = __expf(__bfloat162float(x1.x));
        const float ex3 = __expf(__bfloat162float(x1.y));
        const float eg0 = __expf(__bfloat162float(g0.x));
        const float eg1 = __expf(__bfloat162float(g0.y));
        const float eg2 = __expf(__bfloat162float(g1.x));
        const float eg3 = __expf(__bfloat162float(g1.y));
        s1 += ex0 + ex1 + ex2 + ex3;
        s2 += eg0 + eg1 + eg2 + eg3;
        prod[t * 4 + 0] = ex0 * eg0;
        prod[t * 4 + 1] = ex1 * eg1;
        prod[t * 4 + 2] = ex2 * eg2;
        prod[t * 4 + 3] = ex3 * eg3;
    }
    __syncthreads();
    const float Zx = blk_sum(s1, red);
    const float Zg = blk_sum(s2, red);
    const float invZZ = 1.f / (Zx * Zg);

    __nv_bfloat16* vo = g_V + (size_t)row * HW;
    float s = 0.f;
    for (int t = tid; t < HW; t += 256) {
        const float p = prod[t] * invZZ;
        const float vv = p * (1.f + p * (0.5f + p * (0.16666667f
                         + p * (0.04166667f + p * 0.00833333f))));
        s += vv;
        vo[t] = __float2bfloat16(vv);
    }
    const float Z2 = (float)HW + blk_sum(s, red);
    if (tid == 0) g_invZ2[row] = 1.f / Z2;
}

// ---------------------------------------------------------------------------
// fold: 2048 blocks x 8 rows; two-stage colsum reduction (no atomics)
// ---------------------------------------------------------------------------
__global__ void fold_kernel() {
    const int blk = blockIdx.x;              // 0..2047  (512 blocks per batch)
    const int bat = blk >> 9;
    const int i0 = (blk & 511) * 8;
    const int c = threadIdx.x;               // 0..255
    const float* X = g_X3 + ((size_t)bat * HW + i0) * CH;
    __nv_bfloat16* P = g_X3p + ((size_t)bat * HW + i0) * CH;
    const float* iz = g_invZ2 + bat * HW + i0;
    float s = 0.f;
#pragma unroll
    for (int r = 0; r < 8; r++) {
        const float val = X[(size_t)r * CH + c] * iz[r];
        s += val;
        P[(size_t)r * CH + c] = __float2bfloat16(val);
    }
    g_colpart[blk * CH + c] = s;
}
__global__ void colsum_stage1() {
    const int blk = blockIdx.x;              // 0..127  (16 per... 32 per batch)
    const int c = threadIdx.x;
    float s = 0.f;
#pragma unroll 4
    for (int k = 0; k < 16; k++) s += g_colpart[(blk * 16 + k) * CH + c];
    g_colpart2[blk * CH + c] = s;
}
__global__ void colsum_reduce() {
    const int bat = blockIdx.x, c = threadIdx.x;
    float s = 0.f;
#pragma unroll
    for (int k = 0; k < 32; k++) s += g_colpart2[(bat * 32 + k) * CH + c];
    g_colsum[bat * CH + c] = s;
}

// ---------------------------------------------------------------------------
// out_ms: 4-stage cp.async pipelined output GEMM (port of score_ms scheme)
// grid (2, 32, 4); dynamic smem 4 stages x (V 32x136 + X 32x136) = 69632 B
// ---------------------------------------------------------------------------
#define OT_TILE 4352   // 32 * 136

__global__ __launch_bounds__(256) void out_ms(const float* __restrict__ x_in,
                                              float* __restrict__ out) {
    extern __shared__ __align__(16) __nv_bfloat16 osm[];
    __nv_bfloat16* Vsm = osm;
    __nv_bfloat16* Xsm = osm + 4 * OT_TILE;
    __shared__ float cs_s[128];
    const int bat = blockIdx.z;
    const int j0 = blockIdx.y * 128, c0 = blockIdx.x * 128;
    const __nv_bfloat16* V = g_V + (size_t)bat * HW * HW;      // [i][j]
    const __nv_bfloat16* X = g_X3p + (size_t)bat * HW * CH;    // [i][c]
    const int tid = threadIdx.x, lane = tid & 31, wid = tid >> 5;
    const int wm = wid & 1, wn = wid >> 1;
    const int vrow = tid >> 3;          // 0..31
    const int vch = (tid & 7) * 2;

    if (tid < 128) cs_s[tid] = g_colsum[bat * CH + c0 + tid];

    // prefetch stages 0..2
#pragma unroll
    for (int s = 0; s < 3; s++) {
        const int i0 = s * 32;
        __nv_bfloat16* Vd = Vsm + s * OT_TILE;
        __nv_bfloat16* Xd = Xsm + s * OT_TILE;
#pragma unroll
        for (int q = 0; q < 2; q++) {
            cpa16(&Vd[vrow * 136 + (vch + q) * 8],
                  V + (size_t)(i0 + vrow) * HW + j0 + (vch + q) * 8);
            cpa16(&Xd[vrow * 136 + (vch + q) * 8],
                  X + (size_t)(i0 + vrow) * CH + c0 + (vch + q) * 8);
        }
        CP_COMMIT;
    }

    float acc[4][4][4] = {};
#pragma unroll 1
    for (int s = 0; s < 128; s++) {
        CP_WAIT2;
        __syncthreads();
        const int st = s & 3;
        const __nv_bfloat16* Vp = Vsm + st * OT_TILE;
        const __nv_bfloat16* Xp = Xsm + st * OT_TILE;
#pragma unroll
        for (int kk = 0; kk < 2; kk++) {
            uint32_t a[4][4], b[4][2];
#pragma unroll
            for (int mf = 0; mf < 4; mf++) {
                const int row = kk * 16 + (lane & 7) + (lane >> 4) * 8;
                const int col = wm * 64 + mf * 16 + ((lane >> 3) & 1) * 8;
                ldsm4t(a[mf], cvta_s(&Vp[row * 136 + col]));
            }
#pragma unroll
            for (int np = 0; np < 2; np++) {
                const int row = kk * 16 + (lane & 7) + ((lane >> 3) & 1) * 8;
                const int col = wn * 32 + np * 16 + (lane >> 4) * 8;
                uint32_t r[4];
                ldsm4t(r, cvta_s(&Xp[row * 136 + col]));
                b[2 * np][0] = r[0]; b[2 * np][1] = r[1];
                b[2 * np + 1][0] = r[2]; b[2 * np + 1][1] = r[3];
            }
#pragma unroll
            for (int mf = 0; mf < 4; mf++)
#pragma unroll
                for (int nf = 0; nf < 4; nf++) mma16816(acc[mf][nf], a[mf], b[nf]);
        }
        if (s < 125) {
            const int i0 = (s + 3) * 32, st2 = (s + 3) & 3;
            __nv_bfloat16* Vd = Vsm + st2 * OT_TILE;
            __nv_bfloat16* Xd = Xsm + st2 * OT_TILE;
#pragma unroll
            for (int q = 0; q < 2; q++) {
                cpa16(&Vd[vrow * 136 + (vch + q) * 8],
                      V + (size_t)(i0 + vrow) * HW + j0 + (vch + q) * 8);
                cpa16(&Xd[vrow * 136 + (vch + q) * 8],
                      X + (size_t)(i0 + vrow) * CH + c0 + (vch + q) * 8);
            }
        }
        CP_COMMIT;
    }

#pragma unroll
    for (int mf = 0; mf < 4; mf++) {
        const int j = j0 + wm * 64 + mf * 16 + (lane >> 2);
#pragma unroll
        for (int nf = 0; nf < 4; nf++) {
            const int cc = wn * 32 + nf * 8 + (lane & 3) * 2;
            const size_t b0 = ((size_t)bat * HW + j) * CH + c0 + cc;
            float2 xv = *(const float2*)&x_in[b0];
            float2 o;
            o.x = acc[mf][nf][0] + xv.x + cs_s[cc];
            o.y = acc[mf][nf][1] + xv.y + cs_s[cc + 1];
            *(float2*)&out[b0] = o;
            const size_t b1 = ((size_t)bat * HW + j + 8) * CH + c0 + cc;
            float2 xv2 = *(const float2*)&x_in[b1];
            float2 o2;
            o2.x = acc[mf][nf][2] + xv2.x + cs_s[cc];
            o2.y = acc[mf][nf][3] + xv2.y + cs_s[cc + 1];
            *(float2*)&out[b1] = o2;
        }
    }
}
#define OT_SMEM_BYTES (8 * OT_TILE * 2)   // 69632

// ---------------------------------------------------------------------------
extern "C" void kernel_launch(void* const* d_in, const int* in_sizes, int n_in,
                              void* d_out, int out_size) {
    (void)in_sizes; (void)n_in; (void)out_size;
    const float* x   = (const float*)d_in[0];
    const float* g   = (const float*)d_in[1];
    float* out = (float*)d_out;

    dim3 pg(CH / 128, (BATCH * HW) / 128, 5);
    proj_mma_f32<<<pg, 256>>>(x, g,
        (const float*)d_in[2],  (const float*)d_in[3],
        (const float*)d_in[4],  (const float*)d_in[5],
        (const float*)d_in[6],  (const float*)d_in[7],
        (const float*)d_in[8],  (const float*)d_in[9],
        (const float*)d_in[10], (const float*)d_in[11]);

    cudaFuncSetAttribute(score_ms, cudaFuncAttributeMaxDynamicSharedMemorySize,
                         SC_SMEM_BYTES);
    score_ms<<<dim3(32, 32, 8), 256, SC_SMEM_BYTES>>>();

    row_stats_kernel<<<BATCH * HW, 256>>>();
    fold_kernel<<<2048, 256>>>();
    colsum_stage1<<<128, 256>>>();
    colsum_reduce<<<BATCH, 256>>>();

    cudaFuncSetAttribute(out_ms, cudaFuncAttributeMaxDynamicSharedMemorySize,
                         OT_SMEM_BYTES);
    out_ms<<<dim3(CH / 128, HW / 128, BATCH), 256, OT_SMEM_BYTES>>>(x, out);
}